// round 9
// baseline (speedup 1.0000x reference)
#include <cuda_runtime.h>
#include <math.h>
#include <stdint.h>

// ---------------- problem constants ----------------
#define NR 2000
#define NP 1512
#define NM 3512            // NR + NP
#define NSAMP 8192
#define SPLITK 4

#define E_P_OFS  ((size_t)NR * 512)                 // 1,024,000
#define OUT_OFS  (E_P_OFS + (size_t)NP * 512)       // 1,798,144
#define FLAT_OFS (OUT_OFS + (size_t)NSAMP * 2)      // 1,814,528

typedef unsigned long long ull;

// ---------------- scratch (no allocations allowed) ----------------
__device__ float g_h_att[(size_t)NM * 2048];
__device__ float g_h_fun[(size_t)NM * 4096];
__device__ float g_part_att[(size_t)SPLITK * NM * 256];
__device__ float g_part_fun[(size_t)SPLITK * NM * 256];

// conv weights/biases in constant memory
__constant__ float c_w1[240];    // [16][3][5]
__constant__ float c_b1[16];
__constant__ float c_w2[7680];   // [32][16][3][5]
__constant__ float c_b2[32];
__constant__ float c_bout[2];

__device__ __forceinline__ float gelu_exact(float x) {
    return 0.5f * x * (1.0f + erff(x * 0.70710678118654752440f));
}

// ---------------- packed f32x2 helpers (sm_103a) ----------------
__device__ __forceinline__ ull packf2(float lo, float hi) {
    ull r; asm("mov.b64 %0, {%1,%2};" : "=l"(r) : "f"(lo), "f"(hi)); return r;
}
__device__ __forceinline__ void unpackf2(ull v, float& lo, float& hi) {
    asm("mov.b64 {%0,%1}, %2;" : "=f"(lo), "=f"(hi) : "l"(v));
}
__device__ __forceinline__ void ffma2(ull& d, ull a, ull b) {
    asm("fma.rn.f32x2 %0, %1, %2, %0;" : "+l"(d) : "l"(a), "l"(b));
}

// ---------------- async copy + mma helpers ----------------
__device__ __forceinline__ uint32_t sptr(const void* p) {
    return (uint32_t)__cvta_generic_to_shared(p);
}
__device__ __forceinline__ void cpa16(uint32_t d, const void* s, int bytes) {
    asm volatile("cp.async.cg.shared.global [%0], [%1], 16, %2;\n"
                 :: "r"(d), "l"(s), "r"(bytes));
}
__device__ __forceinline__ void cpa4(uint32_t d, const void* s, int bytes) {
    asm volatile("cp.async.ca.shared.global [%0], [%1], 4, %2;\n"
                 :: "r"(d), "l"(s), "r"(bytes));
}
__device__ __forceinline__ void cp_commit() {
    asm volatile("cp.async.commit_group;\n");
}
__device__ __forceinline__ void cp_wait1() {
    asm volatile("cp.async.wait_group 1;\n" ::: "memory");
}
__device__ __forceinline__ void cp_wait0() {
    asm volatile("cp.async.wait_group 0;\n" ::: "memory");
}
__device__ __forceinline__ void mma_tf32(float* d, const uint32_t* a, const uint32_t* b) {
    asm volatile(
        "mma.sync.aligned.m16n8k8.row.col.f32.tf32.tf32.f32 "
        "{%0,%1,%2,%3}, {%4,%5,%6,%7}, {%8,%9}, {%0,%1,%2,%3};\n"
        : "+f"(d[0]), "+f"(d[1]), "+f"(d[2]), "+f"(d[3])
        : "r"(a[0]), "r"(a[1]), "r"(a[2]), "r"(a[3]), "r"(b[0]), "r"(b[1]));
}

// ---------------- tf32 tensor-core GEMM v4 ----------------
// C = act(A @ W + b). A = virtual concat of A0 (n_r rows) then A1, row stride Ktot.
// ACT==0: gelu -> C[M,N].  ACT==2: raw partial -> C + blockIdx.z*M*N (split-K).
// BM=128, BN=128, BK=32, 3-stage cp.async pipeline in dynamic smem.
// 256 threads = 8 warps (4m x 2n), warp tile 32x64; 2 CTAs/SM.
// A smem [m][32] with col ^= (m&7)<<2 ; B smem [k][128] with n ^= (k&3)<<3.
#define AST_W   (128 * 32)
#define BST_W   (32 * 128)
#define STAGE_W (AST_W + BST_W)
#define GEMM_DSMEM (3 * STAGE_W * 4)

#define GEMM_LOAD(st, k0)                                                     \
  {                                                                           \
    uint32_t abase = sm + (uint32_t)(st) * (STAGE_W * 4);                     \
    uint32_t bbase = abase + AST_W * 4;                                       \
    if (A16) {                                                                \
      _Pragma("unroll")                                                       \
      for (int q = 0; q < 4; q++) {                                           \
        int kc = akoff + q * 4;                                               \
        int kq = (k0) + kc;                                                   \
        int bytes = aval ? max(0, min(kend - kq, 4)) * 4 : 0;                 \
        cpa16(abase + (ambase + (kc ^ awz)) * 4, Aptr + (bytes ? kq : 0), bytes); \
      }                                                                       \
    } else {                                                                  \
      _Pragma("unroll")                                                       \
      for (int q = 0; q < 16; q++) {                                          \
        int kc = akoff + q;                                                   \
        int kq = (k0) + kc;                                                   \
        int bytes = (aval && kq < kend) ? 4 : 0;                              \
        cpa4(abase + (ambase + (kc ^ awz)) * 4, Aptr + (bytes ? kq : 0), bytes); \
      }                                                                       \
    }                                                                         \
    {                                                                         \
      int kg = (k0) + bk;                                                     \
      int bytes = (kg < kend) ? 16 : 0;                                       \
      const float* srcB = W + (size_t)(bytes ? kg : kbeg) * N + bn + bn0;     \
      _Pragma("unroll")                                                       \
      for (int q = 0; q < 4; q++) {                                           \
        int dw = bk * 128 + ((bn0 + q * 4) ^ bswz);                           \
        cpa16(bbase + dw * 4, srcB + q * 4, bytes);                           \
      }                                                                       \
    }                                                                         \
    cp_commit();                                                              \
  }

template<int ACT, bool A16>
__global__ void __launch_bounds__(256, 2)
gemm_tf32(const float* __restrict__ A0, const float* __restrict__ A1, int n_r,
          const float* __restrict__ W, const float* __restrict__ bias,
          int M, int N, int Ktot, int Kchunk,
          float* __restrict__ C)
{
    extern __shared__ __align__(16) float smf[];
    const uint32_t sm = sptr(smf);

    const int tid  = threadIdx.x;
    const int lane = tid & 31;
    const int warp = tid >> 5;
    const int bm = blockIdx.x * 128;
    const int bn = blockIdx.y * 128;
    const int wm = (warp & 3) * 32;
    const int wn = (warp >> 2) * 64;
    const int kbeg = blockIdx.z * Kchunk;
    const int kend = min(kbeg + Kchunk, Ktot);

    // A loader: thread t -> row t>>1, k-half (t&1)*16
    const int am = tid >> 1;
    const int arow = bm + am;
    const bool aval = arow < M;
    const float* Aptr;
    {
        int r = aval ? arow : 0;
        Aptr = (r < n_r) ? (A0 + (size_t)r * Ktot)
                         : (A1 + (size_t)(r - n_r) * Ktot);
    }
    const int akoff  = (tid & 1) * 16;
    const int ambase = am * 32;
    const int awz    = (am & 7) << 2;

    // B loader: thread t -> k row t>>3 (0..31), n block (t&7)*16
    const int bk   = tid >> 3;
    const int bn0  = (tid & 7) * 16;
    const int bswz = (bk & 3) << 3;

    float acc[2][8][4];
#pragma unroll
    for (int i = 0; i < 2; i++)
#pragma unroll
        for (int j = 0; j < 8; j++)
#pragma unroll
            for (int q = 0; q < 4; q++) acc[i][j][q] = 0.f;

    const int fr = lane >> 2;
    const int fc = lane & 3;
    const int nT = (kend - kbeg + 31) >> 5;

    GEMM_LOAD(0, kbeg)
    if (nT > 1) GEMM_LOAD(1, kbeg + 32)

    for (int t = 0; t < nT; t++) {
        if (t + 1 < nT) cp_wait1(); else cp_wait0();
        __syncthreads();
        if (t + 2 < nT) {
            GEMM_LOAD((t + 2) % 3, kbeg + (t + 2) * 32)
        }
        const float* as = smf + (t % 3) * STAGE_W;
        const float* bs = as + AST_W;
#pragma unroll
        for (int kq = 0; kq < 4; kq++) {
            uint32_t af[2][4], bf[8][2];
#pragma unroll
            for (int i = 0; i < 2; i++) {
                const int row = wm + i * 16 + fr;
                const int swz = (row & 7) << 2;
                const float* p  = as + row * 32;
                const float* p8 = as + (row + 8) * 32;
                const int c0 = (fc + kq * 8) ^ swz;
                const int c4 = (fc + 4 + kq * 8) ^ swz;
                af[i][0] = __float_as_uint(p[c0]);
                af[i][1] = __float_as_uint(p8[c0]);
                af[i][2] = __float_as_uint(p[c4]);
                af[i][3] = __float_as_uint(p8[c4]);
            }
#pragma unroll
            for (int j = 0; j < 8; j++) {
                const int n = (wn + j * 8 + fr) ^ (fc << 3);
                bf[j][0] = __float_as_uint(bs[(fc + kq * 8) * 128 + n]);
                bf[j][1] = __float_as_uint(bs[(fc + 4 + kq * 8) * 128 + n]);
            }
#pragma unroll
            for (int i = 0; i < 2; i++)
#pragma unroll
                for (int j = 0; j < 8; j++)
                    mma_tf32(acc[i][j], af[i], bf[j]);
        }
    }
    __syncthreads();

    // epilogue
    float* Cb = C;
    if (ACT == 2) Cb += (size_t)blockIdx.z * M * N;
#pragma unroll
    for (int i = 0; i < 2; i++) {
        const int m0 = bm + wm + i * 16 + fr;
#pragma unroll
        for (int j = 0; j < 8; j++) {
            const int n0 = bn + wn + j * 8 + fc * 2;
            float b0 = 0.f, b1 = 0.f;
            if (ACT == 0) { b0 = bias[n0]; b1 = bias[n0 + 1]; }
            if (m0 < M) {
                float v0 = acc[i][j][0] + b0, v1 = acc[i][j][1] + b1;
                if (ACT == 0) { v0 = gelu_exact(v0); v1 = gelu_exact(v1); }
                Cb[(size_t)m0 * N + n0]     = v0;
                Cb[(size_t)m0 * N + n0 + 1] = v1;
            }
            if (m0 + 8 < M) {
                float v2 = acc[i][j][2] + b0, v3 = acc[i][j][3] + b1;
                if (ACT == 0) { v2 = gelu_exact(v2); v3 = gelu_exact(v3); }
                Cb[(size_t)(m0 + 8) * N + n0]     = v2;
                Cb[(size_t)(m0 + 8) * N + n0 + 1] = v3;
            }
        }
    }
}

// ---------------- layer-2 split-K reduce + bias + sigmoid + scatter ----------------
__global__ void __launch_bounds__(256)
l2_epilogue(const float* __restrict__ pa, const float* __restrict__ pf,
            const float* __restrict__ ba, const float* __restrict__ bf,
            float* __restrict__ d_out)
{
    int t = blockIdx.x * blockDim.x + threadIdx.x;
    if (t >= NM * 128) return;
    int m  = t >> 7;
    int c4 = (t & 127) * 4;
    const float* src;
    const float* bb;
    int c;
    if (c4 < 256) { src = pa + (size_t)m * 256 + c4;         bb = ba; c = c4; }
    else          { src = pf + (size_t)m * 256 + (c4 - 256); bb = bf; c = c4 - 256; }
    float v[4];
#pragma unroll
    for (int q = 0; q < 4; q++) {
        float s = bb[c + q];
#pragma unroll
        for (int sk = 0; sk < SPLITK; sk++)
            s += src[(size_t)sk * NM * 256 + q];
        v[q] = 1.f / (1.f + expf(-s));
    }
    size_t dst = (m < NR) ? ((size_t)m * 512 + c4)
                          : (E_P_OFS + (size_t)(m - NR) * 512 + c4);
    *(float4*)(d_out + dst) = make_float4(v[0], v[1], v[2], v[3]);
}

// ---------------- fused gather + conv1/pool + conv2(f32x2)/pool + tanh + out GEMV ----------------
__global__ void __launch_bounds__(256)
conv_kernel(const int* __restrict__ idx, const float* __restrict__ W_out,
            float* __restrict__ d_out)
{
    __shared__ float xp[2][516];        // input rows with halo (index iw+2)
    __shared__ float h1p[16][2][260];   // pooled conv1 with halo (index pw+2)
    __shared__ float red[16];

    const int s = blockIdx.x;
    const int tid = threadIdx.x;
    const int w = tid >> 5, l = tid & 31;

    const int id = idx[s];
    const int r_no = id / 1512;
    const int p_no = id % 1512;
    const float* er = d_out + (size_t)r_no * 512;
    const float* ep = d_out + E_P_OFS + (size_t)p_no * 512;

    for (int t = tid; t < 2 * 516; t += 256) {
        int row = (t >= 516);
        int c = row ? (t - 516) : t;
        int iw = c - 2;
        float v = 0.f;
        if (iw >= 0 && iw < 512) v = row ? ep[iw] : er[iw];
        xp[row][c] = v;
    }
    if (tid < 128) {
        int ic = tid >> 3, rem = tid & 7;
        int ih = rem >> 2, e = rem & 3;
        int c = (e < 2) ? e : (256 + e);
        h1p[ic][ih][c] = 0.f;
    }
    __syncthreads();

    // ---- conv1 (3x5, pad 2) + leaky + avgpool(2x2) ----
#pragma unroll
    for (int ph = 0; ph < 2; ph++) {
#pragma unroll
        for (int j = 0; j < 8; j++) {
            int pw = l + 32 * j;
            float t0[6], t1[6];
#pragma unroll
            for (int q = 0; q < 6; q++) { t0[q] = xp[0][2 * pw + q]; t1[q] = xp[1][2 * pw + q]; }
#pragma unroll
            for (int oi = 0; oi < 2; oi++) {
                int oc = w + 8 * oi;
                float b = c_b1[oc];
                float v00 = b, v01 = b, v10 = b, v11 = b;
#pragma unroll
                for (int kw = 0; kw < 5; kw++) {
                    float w0 = c_w1[oc * 15 + 0 + kw];
                    float w1 = c_w1[oc * 15 + 5 + kw];
                    float w2 = c_w1[oc * 15 + 10 + kw];
                    if (ph == 0) {
                        v00 += t0[kw] * w2;                 v01 += t0[kw + 1] * w2;
                        v10 += t0[kw] * w1 + t1[kw] * w2;   v11 += t0[kw + 1] * w1 + t1[kw + 1] * w2;
                    } else {
                        v00 += t0[kw] * w0 + t1[kw] * w1;   v01 += t0[kw + 1] * w0 + t1[kw + 1] * w1;
                        v10 += t1[kw] * w0;                 v11 += t1[kw + 1] * w0;
                    }
                }
                float lk00 = v00 >= 0.f ? v00 : 0.01f * v00;
                float lk01 = v01 >= 0.f ? v01 : 0.01f * v01;
                float lk10 = v10 >= 0.f ? v10 : 0.01f * v10;
                float lk11 = v11 >= 0.f ? v11 : 0.01f * v11;
                h1p[oc][ph][pw + 2] = 0.25f * (lk00 + lk01 + lk10 + lk11);
            }
        }
    }
    __syncthreads();

    // ---- conv2 (packed f32x2) + leaky + maxpool + tanh + out dot ----
    float p0 = 0.f, p1 = 0.f;
#pragma unroll 1
    for (int oig = 0; oig < 2; oig++) {
        ull accp[2][4][4];
#pragma unroll
        for (int a = 0; a < 2; a++) {
            float b = c_b2[w + 8 * a + 16 * oig];
            ull bp = packf2(b, b);
#pragma unroll
            for (int oh = 0; oh < 4; oh++)
#pragma unroll
                for (int jp = 0; jp < 4; jp++) accp[a][oh][jp] = bp;
        }
#pragma unroll 1
        for (int ic = 0; ic < 16; ic++) {
            ull wgp[2][15];
#pragma unroll
            for (int a = 0; a < 2; a++) {
                int oc = w + 8 * a + 16 * oig;
                const float* cw = c_w2 + ((size_t)oc * 16 + ic) * 15;
#pragma unroll
                for (int q = 0; q < 15; q++) { float c = cw[q]; wgp[a][q] = packf2(c, c); }
            }
#pragma unroll
            for (int jp = 0; jp < 4; jp++) {
                int owA = l + 32 * jp;
                int owB = owA + 128;
                ull pu0[5], pu1[5];
#pragma unroll
                for (int q = 0; q < 5; q++) {
                    pu0[q] = packf2(h1p[ic][0][owA + q], h1p[ic][0][owB + q]);
                    pu1[q] = packf2(h1p[ic][1][owA + q], h1p[ic][1][owB + q]);
                }
#pragma unroll
                for (int a = 0; a < 2; a++) {
#pragma unroll
                    for (int kw = 0; kw < 5; kw++) {
                        ull w0 = wgp[a][kw], w1 = wgp[a][5 + kw], w2 = wgp[a][10 + kw];
                        ffma2(accp[a][0][jp], pu0[kw], w2);
                        ffma2(accp[a][1][jp], pu0[kw], w1);
                        ffma2(accp[a][1][jp], pu1[kw], w2);
                        ffma2(accp[a][2][jp], pu0[kw], w0);
                        ffma2(accp[a][2][jp], pu1[kw], w1);
                        ffma2(accp[a][3][jp], pu1[kw], w0);
                    }
                }
            }
        }
#pragma unroll
        for (int a = 0; a < 2; a++) {
            int oc = w + 8 * a + 16 * oig;
#pragma unroll
            for (int ph = 0; ph < 2; ph++) {
#pragma unroll
                for (int jp = 0; jp < 4; jp++) {
                    float lo0, hi0, lo1, hi1;
                    unpackf2(accp[a][2 * ph][jp],     lo0, hi0);
                    unpackf2(accp[a][2 * ph + 1][jp], lo1, hi1);
#pragma unroll
                    for (int half = 0; half < 2; half++) {
                        int j = jp + 4 * half;
                        float m = half ? fmaxf(hi0, hi1) : fmaxf(lo0, lo1);
                        float o = __shfl_xor_sync(0xffffffffu, m, 1);
                        m = fmaxf(m, o);
                        if ((l & 1) == 0) {
                            float lv = m >= 0.f ? m : 0.01f * m;
                            float val = tanhf(lv);
                            int pw = (l >> 1) + 16 * j;
                            int fidx = oc * 256 + ph * 128 + pw;
                            d_out[FLAT_OFS + (size_t)s * 8192 + fidx] = val;
                            p0 += val * __ldg(W_out + 2 * fidx);
                            p1 += val * __ldg(W_out + 2 * fidx + 1);
                        }
                    }
                }
            }
        }
    }

#pragma unroll
    for (int off = 16; off > 0; off >>= 1) {
        p0 += __shfl_xor_sync(0xffffffffu, p0, off);
        p1 += __shfl_xor_sync(0xffffffffu, p1, off);
    }
    if (l == 0) { red[w] = p0; red[8 + w] = p1; }
    __syncthreads();
    if (tid == 0) {
        float s0 = c_bout[0], s1 = c_bout[1];
#pragma unroll
        for (int q = 0; q < 8; q++) { s0 += red[q]; s1 += red[8 + q]; }
        d_out[OUT_OFS + 2 * (size_t)s]     = s0;
        d_out[OUT_OFS + 2 * (size_t)s + 1] = s1;
    }
}

// ---------------- launch ----------------
extern "C" void kernel_launch(void* const* d_in, const int* in_sizes, int n_in,
                              void* d_out_, int out_size)
{
    (void)in_sizes; (void)n_in; (void)out_size;
    const float* r_att  = (const float*)d_in[0];
    const float* p_att  = (const float*)d_in[1];
    const float* r_fun  = (const float*)d_in[2];
    const float* p_fun  = (const float*)d_in[3];
    const int*   idx    = (const int*)d_in[4];
    const float* W_att1 = (const float*)d_in[5];
    const float* b_att1 = (const float*)d_in[6];
    const float* W_att2 = (const float*)d_in[7];
    const float* b_att2 = (const float*)d_in[8];
    const float* W_fun1 = (const float*)d_in[9];
    const float* b_fun1 = (const float*)d_in[10];
    const float* W_fun2 = (const float*)d_in[11];
    const float* b_fun2 = (const float*)d_in[12];
    const float* W_out  = (const float*)d_in[17];
    float* d_out = (float*)d_out_;

    cudaMemcpyToSymbolAsync(c_w1,   d_in[13], 240  * sizeof(float), 0, cudaMemcpyDeviceToDevice);
    cudaMemcpyToSymbolAsync(c_b1,   d_in[14], 16   * sizeof(float), 0, cudaMemcpyDeviceToDevice);
    cudaMemcpyToSymbolAsync(c_w2,   d_in[15], 7680 * sizeof(float), 0, cudaMemcpyDeviceToDevice);
    cudaMemcpyToSymbolAsync(c_b2,   d_in[16], 32   * sizeof(float), 0, cudaMemcpyDeviceToDevice);
    cudaMemcpyToSymbolAsync(c_bout, d_in[18], 2    * sizeof(float), 0, cudaMemcpyDeviceToDevice);

    float *h_att_p = 0, *h_fun_p = 0, *pa = 0, *pf = 0;
    cudaGetSymbolAddress((void**)&h_att_p, g_h_att);
    cudaGetSymbolAddress((void**)&h_fun_p, g_h_fun);
    cudaGetSymbolAddress((void**)&pa, g_part_att);
    cudaGetSymbolAddress((void**)&pf, g_part_fun);

    cudaFuncSetAttribute(gemm_tf32<0, true >, cudaFuncAttributeMaxDynamicSharedMemorySize, GEMM_DSMEM);
    cudaFuncSetAttribute(gemm_tf32<0, false>, cudaFuncAttributeMaxDynamicSharedMemorySize, GEMM_DSMEM);
    cudaFuncSetAttribute(gemm_tf32<2, true >, cudaFuncAttributeMaxDynamicSharedMemorySize, GEMM_DSMEM);

    dim3 blk(256);
    // layer 1: gelu.  grid.x = m-blocks (28), grid.y = n-blocks (BN=128).
    gemm_tf32<0, true ><<<dim3(28, 2048 / 128, 1), blk, GEMM_DSMEM>>>(
        r_att, p_att, NR, W_att1, b_att1, NM, 2048, 3000, 3000, h_att_p);
    gemm_tf32<0, false><<<dim3(28, 4096 / 128, 1), blk, GEMM_DSMEM>>>(
        r_fun, p_fun, NR, W_fun1, b_fun1, NM, 4096, 5603, 5603, h_fun_p);
    // layer 2: split-K raw partials (N=256 -> 2 n-blocks)
    gemm_tf32<2, true><<<dim3(28, 2, SPLITK), blk, GEMM_DSMEM>>>(
        h_att_p, h_att_p, NM, W_att2, b_att2, NM, 256, 2048, 2048 / SPLITK, pa);
    gemm_tf32<2, true><<<dim3(28, 2, SPLITK), blk, GEMM_DSMEM>>>(
        h_fun_p, h_fun_p, NM, W_fun2, b_fun2, NM, 256, 4096, 4096 / SPLITK, pf);
    // reduce + bias + sigmoid + scatter to e_r / e_p
    l2_epilogue<<<(NM * 128 + 255) / 256, 256>>>(pa, pf, b_att2, b_fun2, d_out);
    // conv stage
    conv_kernel<<<NSAMP, blk>>>(idx, W_out, d_out);
}

// round 10
// speedup vs baseline: 1.0363x; 1.0363x over previous
#include <cuda_runtime.h>
#include <math.h>
#include <stdint.h>

// ---------------- problem constants ----------------
#define NR 2000
#define NP 1512
#define NM 3512            // NR + NP
#define NSAMP 8192
#define SPLITK 4

#define E_P_OFS  ((size_t)NR * 512)                 // 1,024,000
#define OUT_OFS  (E_P_OFS + (size_t)NP * 512)       // 1,798,144
#define FLAT_OFS (OUT_OFS + (size_t)NSAMP * 2)      // 1,814,528

typedef unsigned long long ull;

// ---------------- scratch (no allocations allowed) ----------------
__device__ float g_h_att[(size_t)NM * 2048];
__device__ float g_h_fun[(size_t)NM * 4096];
__device__ float g_part_att[(size_t)SPLITK * NM * 256];
__device__ float g_part_fun[(size_t)SPLITK * NM * 256];

// conv weights/biases in constant memory
__constant__ float c_w1[240];    // [16][3][5]
__constant__ float c_b1[16];
__constant__ float c_w2[7680];   // [32][16][3][5]
__constant__ float c_b2[32];
__constant__ float c_bout[2];

__device__ __forceinline__ float gelu_exact(float x) {
    return 0.5f * x * (1.0f + erff(x * 0.70710678118654752440f));
}

// ---------------- packed f32x2 helpers (sm_103a) ----------------
__device__ __forceinline__ ull packf2(float lo, float hi) {
    ull r; asm("mov.b64 %0, {%1,%2};" : "=l"(r) : "f"(lo), "f"(hi)); return r;
}
__device__ __forceinline__ void unpackf2(ull v, float& lo, float& hi) {
    asm("mov.b64 {%0,%1}, %2;" : "=f"(lo), "=f"(hi) : "l"(v));
}
__device__ __forceinline__ void ffma2(ull& d, ull a, ull b) {
    asm("fma.rn.f32x2 %0, %1, %2, %0;" : "+l"(d) : "l"(a), "l"(b));
}

// ---------------- async copy + mma helpers ----------------
__device__ __forceinline__ uint32_t sptr(const void* p) {
    return (uint32_t)__cvta_generic_to_shared(p);
}
__device__ __forceinline__ void cpa16(uint32_t d, const void* s, int bytes) {
    asm volatile("cp.async.cg.shared.global [%0], [%1], 16, %2;\n"
                 :: "r"(d), "l"(s), "r"(bytes));
}
__device__ __forceinline__ void cpa4(uint32_t d, const void* s, int bytes) {
    asm volatile("cp.async.ca.shared.global [%0], [%1], 4, %2;\n"
                 :: "r"(d), "l"(s), "r"(bytes));
}
__device__ __forceinline__ void cp_commit() {
    asm volatile("cp.async.commit_group;\n");
}
__device__ __forceinline__ void cp_wait1() {
    asm volatile("cp.async.wait_group 1;\n" ::: "memory");
}
__device__ __forceinline__ void mma_tf32(float* d, const uint32_t* a, const uint32_t* b) {
    asm volatile(
        "mma.sync.aligned.m16n8k8.row.col.f32.tf32.tf32.f32 "
        "{%0,%1,%2,%3}, {%4,%5,%6,%7}, {%8,%9}, {%0,%1,%2,%3};\n"
        : "+f"(d[0]), "+f"(d[1]), "+f"(d[2]), "+f"(d[3])
        : "r"(a[0]), "r"(a[1]), "r"(a[2]), "r"(a[3]), "r"(b[0]), "r"(b[1]));
}

// ---------------- tf32 tensor-core GEMM v5 ----------------
// C = act(A @ W + b). A = virtual concat of A0 (n_r rows) then A1, row stride Ktot.
// ACT==0: gelu -> C[M,N].  ACT==2: raw partial -> C + blockIdx.z*M*N (split-K).
// BM=128, BN=128, BK=16.  128 threads = 4 warps (2m x 2n), warp tile 64x64.
// LDS:MMA = 1:1 (32 LDS per 64 MMA... per kq: 16 A-LDS + 16 B-LDS for 32 MMA).
// 2 CTAs/SM (regs ~190 x 128thr = 24.3K; 2 CTAs fit 64K RF).
// A smem [m][16], col ^= ((m>>1)&3)<<2 ; B smem [k][128], n ^= (k&3)<<3.
#define ASTAGE (128 * 16)
#define BSTAGE (16 * 128)

#define GEMM_LOAD(st, k0)                                                    \
  {                                                                          \
    if (A16) {                                                               \
      _Pragma("unroll")                                                      \
      for (int q = 0; q < 4; q++) {                                          \
        int kq = (k0) + q * 4;                                               \
        int bytes = aval ? max(0, min(kend - kq, 4)) * 4 : 0;                \
        cpa16(sa + ((st) * ASTAGE + ambase + ((q * 4) ^ awz)) * 4,           \
              Aptr + (bytes ? kq : 0), bytes);                               \
      }                                                                      \
    } else {                                                                 \
      _Pragma("unroll")                                                      \
      for (int q = 0; q < 16; q++) {                                         \
        int kq = (k0) + q;                                                   \
        int bytes = (aval && kq < kend) ? 4 : 0;                             \
        cpa4(sa + ((st) * ASTAGE + ambase + (q ^ awz)) * 4,                  \
             Aptr + (bytes ? kq : 0), bytes);                                \
      }                                                                      \
    }                                                                        \
    {                                                                        \
      int kg = (k0) + bk;                                                    \
      int bytes = (kg < kend) ? 16 : 0;                                      \
      const float* srcB = W + (size_t)(bytes ? kg : kbeg) * N + bn + bn0;    \
      _Pragma("unroll")                                                      \
      for (int q = 0; q < 4; q++) {                                          \
        int dw = bk * 128 + ((bn0 + q * 4) ^ bswz);                          \
        cpa16(sb + ((st) * BSTAGE + dw) * 4, srcB + q * 4, bytes);           \
      }                                                                      \
    }                                                                        \
    cp_commit();                                                             \
  }

template<int ACT, bool A16>
__global__ void __launch_bounds__(128, 2)
gemm_tf32(const float* __restrict__ A0, const float* __restrict__ A1, int n_r,
          const float* __restrict__ W, const float* __restrict__ bias,
          int M, int N, int Ktot, int Kchunk,
          float* __restrict__ C)
{
    __shared__ __align__(16) float As[2][ASTAGE];
    __shared__ __align__(16) float Bs[2][BSTAGE];

    const int tid  = threadIdx.x;
    const int lane = tid & 31;
    const int warp = tid >> 5;
    const int bm = blockIdx.x * 128;
    const int bn = blockIdx.y * 128;
    const int wm = (warp >> 1) * 64;
    const int wn = (warp & 1) * 64;
    const int kbeg = blockIdx.z * Kchunk;
    const int kend = min(kbeg + Kchunk, Ktot);

    // A loader: thread t -> row t, all 16 k
    const int am = tid;
    const int arow = bm + am;
    const bool aval = arow < M;
    const float* Aptr;
    {
        int r = aval ? arow : 0;
        Aptr = (r < n_r) ? (A0 + (size_t)r * Ktot)
                         : (A1 + (size_t)(r - n_r) * Ktot);
    }
    const int ambase = am * 16;
    const int awz    = ((am >> 1) & 3) << 2;
    const uint32_t sa = sptr(&As[0][0]);

    // B loader: thread t -> k row t>>3 (0..15), n block (t&7)*16
    const int bk   = tid >> 3;
    const int bn0  = (tid & 7) * 16;
    const int bswz = (bk & 3) << 3;
    const uint32_t sb = sptr(&Bs[0][0]);

    float acc[4][8][4];
#pragma unroll
    for (int i = 0; i < 4; i++)
#pragma unroll
        for (int j = 0; j < 8; j++)
#pragma unroll
            for (int q = 0; q < 4; q++) acc[i][j][q] = 0.f;

    const int fr = lane >> 2;
    const int fc = lane & 3;
    const int nT = (kend - kbeg + 15) >> 4;

    GEMM_LOAD(0, kbeg)

    for (int t = 0; t < nT; t++) {
        if (t + 1 < nT) {
            GEMM_LOAD((t + 1) & 1, kbeg + (t + 1) * 16)
        } else {
            cp_commit();
        }
        cp_wait1();
        __syncthreads();

        const float* as = &As[t & 1][0];
        const float* bs = &Bs[t & 1][0];
#pragma unroll
        for (int kq = 0; kq < 2; kq++) {
            uint32_t af[4][4], bf[8][2];
#pragma unroll
            for (int i = 0; i < 4; i++) {
                const int row = wm + i * 16 + fr;
                const int swz = ((row >> 1) & 3) << 2;
                const float* p  = as + row * 16;
                const float* p8 = as + (row + 8) * 16;
                const int c0 = (fc + kq * 8) ^ swz;
                const int c4 = (fc + 4 + kq * 8) ^ swz;
                af[i][0] = __float_as_uint(p[c0]);
                af[i][1] = __float_as_uint(p8[c0]);
                af[i][2] = __float_as_uint(p[c4]);
                af[i][3] = __float_as_uint(p8[c4]);
            }
#pragma unroll
            for (int j = 0; j < 8; j++) {
                const int n = (wn + j * 8 + fr) ^ (fc << 3);
                bf[j][0] = __float_as_uint(bs[(fc + kq * 8) * 128 + n]);
                bf[j][1] = __float_as_uint(bs[(fc + 4 + kq * 8) * 128 + n]);
            }
#pragma unroll
            for (int i = 0; i < 4; i++)
#pragma unroll
                for (int j = 0; j < 8; j++)
                    mma_tf32(acc[i][j], af[i], bf[j]);
        }
        __syncthreads();
    }

    // epilogue
    float* Cb = C;
    if (ACT == 2) Cb += (size_t)blockIdx.z * M * N;
#pragma unroll
    for (int i = 0; i < 4; i++) {
        const int m0 = bm + wm + i * 16 + fr;
#pragma unroll
        for (int j = 0; j < 8; j++) {
            const int n0 = bn + wn + j * 8 + fc * 2;
            float b0 = 0.f, b1 = 0.f;
            if (ACT == 0) { b0 = bias[n0]; b1 = bias[n0 + 1]; }
            if (m0 < M) {
                float v0 = acc[i][j][0] + b0, v1 = acc[i][j][1] + b1;
                if (ACT == 0) { v0 = gelu_exact(v0); v1 = gelu_exact(v1); }
                Cb[(size_t)m0 * N + n0]     = v0;
                Cb[(size_t)m0 * N + n0 + 1] = v1;
            }
            if (m0 + 8 < M) {
                float v2 = acc[i][j][2] + b0, v3 = acc[i][j][3] + b1;
                if (ACT == 0) { v2 = gelu_exact(v2); v3 = gelu_exact(v3); }
                Cb[(size_t)(m0 + 8) * N + n0]     = v2;
                Cb[(size_t)(m0 + 8) * N + n0 + 1] = v3;
            }
        }
    }
}

// ---------------- layer-2 split-K reduce + bias + sigmoid + scatter ----------------
__global__ void __launch_bounds__(256)
l2_epilogue(const float* __restrict__ pa, const float* __restrict__ pf,
            const float* __restrict__ ba, const float* __restrict__ bf,
            float* __restrict__ d_out)
{
    int t = blockIdx.x * blockDim.x + threadIdx.x;
    if (t >= NM * 128) return;
    int m  = t >> 7;
    int c4 = (t & 127) * 4;
    const float* src;
    const float* bb;
    int c;
    if (c4 < 256) { src = pa + (size_t)m * 256 + c4;         bb = ba; c = c4; }
    else          { src = pf + (size_t)m * 256 + (c4 - 256); bb = bf; c = c4 - 256; }
    float v[4];
#pragma unroll
    for (int q = 0; q < 4; q++) {
        float s = bb[c + q];
#pragma unroll
        for (int sk = 0; sk < SPLITK; sk++)
            s += src[(size_t)sk * NM * 256 + q];
        v[q] = 1.f / (1.f + expf(-s));
    }
    size_t dst = (m < NR) ? ((size_t)m * 512 + c4)
                          : (E_P_OFS + (size_t)(m - NR) * 512 + c4);
    *(float4*)(d_out + dst) = make_float4(v[0], v[1], v[2], v[3]);
}

// ---------------- fused gather + conv1/pool + conv2(f32x2)/pool + tanh + out GEMV ----------------
__global__ void __launch_bounds__(256)
conv_kernel(const int* __restrict__ idx, const float* __restrict__ W_out,
            float* __restrict__ d_out)
{
    __shared__ float xp[2][516];        // input rows with halo (index iw+2)
    __shared__ float h1p[16][2][260];   // pooled conv1 with halo (index pw+2)
    __shared__ float red[16];

    const int s = blockIdx.x;
    const int tid = threadIdx.x;
    const int w = tid >> 5, l = tid & 31;

    const int id = idx[s];
    const int r_no = id / 1512;
    const int p_no = id % 1512;
    const float* er = d_out + (size_t)r_no * 512;
    const float* ep = d_out + E_P_OFS + (size_t)p_no * 512;

    for (int t = tid; t < 2 * 516; t += 256) {
        int row = (t >= 516);
        int c = row ? (t - 516) : t;
        int iw = c - 2;
        float v = 0.f;
        if (iw >= 0 && iw < 512) v = row ? ep[iw] : er[iw];
        xp[row][c] = v;
    }
    if (tid < 128) {
        int ic = tid >> 3, rem = tid & 7;
        int ih = rem >> 2, e = rem & 3;
        int c = (e < 2) ? e : (256 + e);
        h1p[ic][ih][c] = 0.f;
    }
    __syncthreads();

    // ---- conv1 (3x5, pad 2) + leaky + avgpool(2x2) ----
#pragma unroll
    for (int ph = 0; ph < 2; ph++) {
#pragma unroll
        for (int j = 0; j < 8; j++) {
            int pw = l + 32 * j;
            float t0[6], t1[6];
#pragma unroll
            for (int q = 0; q < 6; q++) { t0[q] = xp[0][2 * pw + q]; t1[q] = xp[1][2 * pw + q]; }
#pragma unroll
            for (int oi = 0; oi < 2; oi++) {
                int oc = w + 8 * oi;
                float b = c_b1[oc];
                float v00 = b, v01 = b, v10 = b, v11 = b;
#pragma unroll
                for (int kw = 0; kw < 5; kw++) {
                    float w0 = c_w1[oc * 15 + 0 + kw];
                    float w1 = c_w1[oc * 15 + 5 + kw];
                    float w2 = c_w1[oc * 15 + 10 + kw];
                    if (ph == 0) {
                        v00 += t0[kw] * w2;                 v01 += t0[kw + 1] * w2;
                        v10 += t0[kw] * w1 + t1[kw] * w2;   v11 += t0[kw + 1] * w1 + t1[kw + 1] * w2;
                    } else {
                        v00 += t0[kw] * w0 + t1[kw] * w1;   v01 += t0[kw + 1] * w0 + t1[kw + 1] * w1;
                        v10 += t1[kw] * w0;                 v11 += t1[kw + 1] * w0;
                    }
                }
                float lk00 = v00 >= 0.f ? v00 : 0.01f * v00;
                float lk01 = v01 >= 0.f ? v01 : 0.01f * v01;
                float lk10 = v10 >= 0.f ? v10 : 0.01f * v10;
                float lk11 = v11 >= 0.f ? v11 : 0.01f * v11;
                h1p[oc][ph][pw + 2] = 0.25f * (lk00 + lk01 + lk10 + lk11);
            }
        }
    }
    __syncthreads();

    // ---- conv2 (packed f32x2) + leaky + maxpool + tanh + out dot ----
    float p0 = 0.f, p1 = 0.f;
#pragma unroll 1
    for (int oig = 0; oig < 2; oig++) {
        ull accp[2][4][4];
#pragma unroll
        for (int a = 0; a < 2; a++) {
            float b = c_b2[w + 8 * a + 16 * oig];
            ull bp = packf2(b, b);
#pragma unroll
            for (int oh = 0; oh < 4; oh++)
#pragma unroll
                for (int jp = 0; jp < 4; jp++) accp[a][oh][jp] = bp;
        }
#pragma unroll 1
        for (int ic = 0; ic < 16; ic++) {
            ull wgp[2][15];
#pragma unroll
            for (int a = 0; a < 2; a++) {
                int oc = w + 8 * a + 16 * oig;
                const float* cw = c_w2 + ((size_t)oc * 16 + ic) * 15;
#pragma unroll
                for (int q = 0; q < 15; q++) { float c = cw[q]; wgp[a][q] = packf2(c, c); }
            }
#pragma unroll
            for (int jp = 0; jp < 4; jp++) {
                int owA = l + 32 * jp;
                int owB = owA + 128;
                ull pu0[5], pu1[5];
#pragma unroll
                for (int q = 0; q < 5; q++) {
                    pu0[q] = packf2(h1p[ic][0][owA + q], h1p[ic][0][owB + q]);
                    pu1[q] = packf2(h1p[ic][1][owA + q], h1p[ic][1][owB + q]);
                }
#pragma unroll
                for (int a = 0; a < 2; a++) {
#pragma unroll
                    for (int kw = 0; kw < 5; kw++) {
                        ull w0 = wgp[a][kw], w1 = wgp[a][5 + kw], w2 = wgp[a][10 + kw];
                        ffma2(accp[a][0][jp], pu0[kw], w2);
                        ffma2(accp[a][1][jp], pu0[kw], w1);
                        ffma2(accp[a][1][jp], pu1[kw], w2);
                        ffma2(accp[a][2][jp], pu0[kw], w0);
                        ffma2(accp[a][2][jp], pu1[kw], w1);
                        ffma2(accp[a][3][jp], pu1[kw], w0);
                    }
                }
            }
        }
#pragma unroll
        for (int a = 0; a < 2; a++) {
            int oc = w + 8 * a + 16 * oig;
#pragma unroll
            for (int ph = 0; ph < 2; ph++) {
#pragma unroll
                for (int jp = 0; jp < 4; jp++) {
                    float lo0, hi0, lo1, hi1;
                    unpackf2(accp[a][2 * ph][jp],     lo0, hi0);
                    unpackf2(accp[a][2 * ph + 1][jp], lo1, hi1);
#pragma unroll
                    for (int half = 0; half < 2; half++) {
                        int j = jp + 4 * half;
                        float m = half ? fmaxf(hi0, hi1) : fmaxf(lo0, lo1);
                        float o = __shfl_xor_sync(0xffffffffu, m, 1);
                        m = fmaxf(m, o);
                        if ((l & 1) == 0) {
                            float lv = m >= 0.f ? m : 0.01f * m;
                            float val = tanhf(lv);
                            int pw = (l >> 1) + 16 * j;
                            int fidx = oc * 256 + ph * 128 + pw;
                            d_out[FLAT_OFS + (size_t)s * 8192 + fidx] = val;
                            p0 += val * __ldg(W_out + 2 * fidx);
                            p1 += val * __ldg(W_out + 2 * fidx + 1);
                        }
                    }
                }
            }
        }
    }

#pragma unroll
    for (int off = 16; off > 0; off >>= 1) {
        p0 += __shfl_xor_sync(0xffffffffu, p0, off);
        p1 += __shfl_xor_sync(0xffffffffu, p1, off);
    }
    if (l == 0) { red[w] = p0; red[8 + w] = p1; }
    __syncthreads();
    if (tid == 0) {
        float s0 = c_bout[0], s1 = c_bout[1];
#pragma unroll
        for (int q = 0; q < 8; q++) { s0 += red[q]; s1 += red[8 + q]; }
        d_out[OUT_OFS + 2 * (size_t)s]     = s0;
        d_out[OUT_OFS + 2 * (size_t)s + 1] = s1;
    }
}

// ---------------- launch ----------------
extern "C" void kernel_launch(void* const* d_in, const int* in_sizes, int n_in,
                              void* d_out_, int out_size)
{
    (void)in_sizes; (void)n_in; (void)out_size;
    const float* r_att  = (const float*)d_in[0];
    const float* p_att  = (const float*)d_in[1];
    const float* r_fun  = (const float*)d_in[2];
    const float* p_fun  = (const float*)d_in[3];
    const int*   idx    = (const int*)d_in[4];
    const float* W_att1 = (const float*)d_in[5];
    const float* b_att1 = (const float*)d_in[6];
    const float* W_att2 = (const float*)d_in[7];
    const float* b_att2 = (const float*)d_in[8];
    const float* W_fun1 = (const float*)d_in[9];
    const float* b_fun1 = (const float*)d_in[10];
    const float* W_fun2 = (const float*)d_in[11];
    const float* b_fun2 = (const float*)d_in[12];
    const float* W_out  = (const float*)d_in[17];
    float* d_out = (float*)d_out_;

    cudaMemcpyToSymbolAsync(c_w1,   d_in[13], 240  * sizeof(float), 0, cudaMemcpyDeviceToDevice);
    cudaMemcpyToSymbolAsync(c_b1,   d_in[14], 16   * sizeof(float), 0, cudaMemcpyDeviceToDevice);
    cudaMemcpyToSymbolAsync(c_w2,   d_in[15], 7680 * sizeof(float), 0, cudaMemcpyDeviceToDevice);
    cudaMemcpyToSymbolAsync(c_b2,   d_in[16], 32   * sizeof(float), 0, cudaMemcpyDeviceToDevice);
    cudaMemcpyToSymbolAsync(c_bout, d_in[18], 2    * sizeof(float), 0, cudaMemcpyDeviceToDevice);

    float *h_att_p = 0, *h_fun_p = 0, *pa = 0, *pf = 0;
    cudaGetSymbolAddress((void**)&h_att_p, g_h_att);
    cudaGetSymbolAddress((void**)&h_fun_p, g_h_fun);
    cudaGetSymbolAddress((void**)&pa, g_part_att);
    cudaGetSymbolAddress((void**)&pf, g_part_fun);

    dim3 blk(128);
    // layer 1: gelu.  grid.x = m-blocks (28), grid.y = n-blocks (BN=128).
    gemm_tf32<0, true ><<<dim3(28, 2048 / 128, 1), blk>>>(
        r_att, p_att, NR, W_att1, b_att1, NM, 2048, 3000, 3000, h_att_p);
    gemm_tf32<0, false><<<dim3(28, 4096 / 128, 1), blk>>>(
        r_fun, p_fun, NR, W_fun1, b_fun1, NM, 4096, 5603, 5603, h_fun_p);
    // layer 2: split-K raw partials (N=256 -> 2 n-blocks)
    gemm_tf32<2, true><<<dim3(28, 2, SPLITK), blk>>>(
        h_att_p, h_att_p, NM, W_att2, b_att2, NM, 256, 2048, 2048 / SPLITK, pa);
    gemm_tf32<2, true><<<dim3(28, 2, SPLITK), blk>>>(
        h_fun_p, h_fun_p, NM, W_fun2, b_fun2, NM, 256, 4096, 4096 / SPLITK, pf);
    // reduce + bias + sigmoid + scatter to e_r / e_p
    l2_epilogue<<<(NM * 128 + 255) / 256, 256>>>(pa, pf, b_att2, b_fun2, d_out);
    // conv stage
    conv_kernel<<<NSAMP, 256>>>(idx, W_out, d_out);
}

// round 11
// speedup vs baseline: 1.0598x; 1.0227x over previous
#include <cuda_runtime.h>
#include <math.h>
#include <stdint.h>

// ---------------- problem constants ----------------
#define NR 2000
#define NP 1512
#define NM 3512            // NR + NP
#define NSAMP 8192
#define SPLITK 4

#define E_P_OFS  ((size_t)NR * 512)                 // 1,024,000
#define OUT_OFS  (E_P_OFS + (size_t)NP * 512)       // 1,798,144
#define FLAT_OFS (OUT_OFS + (size_t)NSAMP * 2)      // 1,814,528

typedef unsigned long long ull;

// ---------------- scratch (no allocations allowed) ----------------
__device__ float g_h_att[(size_t)NM * 2048];
__device__ float g_h_fun[(size_t)NM * 4096];
__device__ float g_part_att[(size_t)SPLITK * NM * 256];
__device__ float g_part_fun[(size_t)SPLITK * NM * 256];

// conv weights/biases in constant memory
__constant__ float c_w1[240];    // [16][3][5]
__constant__ float c_b1[16];
__constant__ float c_w2[7680];   // [32][16][3][5]
__constant__ float c_b2[32];
__constant__ float c_bout[2];

__device__ __forceinline__ float gelu_exact(float x) {
    return 0.5f * x * (1.0f + erff(x * 0.70710678118654752440f));
}

// ---------------- packed f32x2 helpers (sm_103a) ----------------
__device__ __forceinline__ ull packf2(float lo, float hi) {
    ull r; asm("mov.b64 %0, {%1,%2};" : "=l"(r) : "f"(lo), "f"(hi)); return r;
}
__device__ __forceinline__ void unpackf2(ull v, float& lo, float& hi) {
    asm("mov.b64 {%0,%1}, %2;" : "=f"(lo), "=f"(hi) : "l"(v));
}
__device__ __forceinline__ void ffma2(ull& d, ull a, ull b) {
    asm("fma.rn.f32x2 %0, %1, %2, %0;" : "+l"(d) : "l"(a), "l"(b));
}

// ---------------- async copy + mma helpers ----------------
__device__ __forceinline__ uint32_t sptr(const void* p) {
    return (uint32_t)__cvta_generic_to_shared(p);
}
__device__ __forceinline__ void cpa16(uint32_t d, const void* s, int bytes) {
    asm volatile("cp.async.cg.shared.global [%0], [%1], 16, %2;\n"
                 :: "r"(d), "l"(s), "r"(bytes));
}
__device__ __forceinline__ void cpa4(uint32_t d, const void* s, int bytes) {
    asm volatile("cp.async.ca.shared.global [%0], [%1], 4, %2;\n"
                 :: "r"(d), "l"(s), "r"(bytes));
}
__device__ __forceinline__ void cp_commit() {
    asm volatile("cp.async.commit_group;\n");
}
__device__ __forceinline__ void cp_wait1() {
    asm volatile("cp.async.wait_group 1;\n" ::: "memory");
}
__device__ __forceinline__ void mma_tf32(float* d, const uint32_t* a, const uint32_t* b) {
    asm volatile(
        "mma.sync.aligned.m16n8k8.row.col.f32.tf32.tf32.f32 "
        "{%0,%1,%2,%3}, {%4,%5,%6,%7}, {%8,%9}, {%0,%1,%2,%3};\n"
        : "+f"(d[0]), "+f"(d[1]), "+f"(d[2]), "+f"(d[3])
        : "r"(a[0]), "r"(a[1]), "r"(a[2]), "r"(a[3]), "r"(b[0]), "r"(b[1]));
}

// ---------------- merged tf32 tensor-core GEMM (round-7 body) ----------------
// C = act(A @ W + b). A = virtual concat of A0 (n_r rows) then A1, row stride Ktot.
// ACT==0: gelu -> C[M,N].  ACT==2: raw partial -> C + sk*M*N (split-K).
// BM=128, BN=128, BK=16. 256 threads = 8 warps (4m x 2n), warp tile 32x64; 2 CTAs/SM.
// A smem [m][16], col ^= ((m>>1)&3)<<2 ; B smem [k][128], n ^= (k&3)<<3.
// TWO problems fused per launch: blockIdx.x < nblkA -> problem Pa, else Pb.
// block decode: mb = b%28 ; r = b/28 ; nb = r % nN ; sk = r / nN.
#define ASTAGE (128 * 16)
#define BSTAGE (16 * 128)

struct GP {
    const float *A0, *A1, *W, *bias;
    float *C;
    int n_r, M, N, Ktot, Kchunk, nN, a16;
};

#define GEMM_LOAD(st, k0)                                                    \
  {                                                                          \
    if (P.a16) {                                                             \
      _Pragma("unroll")                                                      \
      for (int q = 0; q < 2; q++) {                                          \
        int kc = akoff + q * 4;                                              \
        int kq = (k0) + kc;                                                  \
        int bytes = aval ? max(0, min(kend - kq, 4)) * 4 : 0;                \
        cpa16(sa + ((st) * ASTAGE + ambase + (kc ^ awz)) * 4,                \
              Aptr + (bytes ? kq : 0), bytes);                               \
      }                                                                      \
    } else {                                                                 \
      _Pragma("unroll")                                                      \
      for (int q = 0; q < 8; q++) {                                          \
        int kc = akoff + q;                                                  \
        int kq = (k0) + kc;                                                  \
        int bytes = (aval && kq < kend) ? 4 : 0;                             \
        cpa4(sa + ((st) * ASTAGE + ambase + (kc ^ awz)) * 4,                 \
             Aptr + (bytes ? kq : 0), bytes);                                \
      }                                                                      \
    }                                                                        \
    {                                                                        \
      int kg = (k0) + bk;                                                    \
      int bytes = (kg < kend) ? 16 : 0;                                      \
      const float* srcB = P.W + (size_t)(bytes ? kg : kbeg) * P.N + bn + bn0;\
      _Pragma("unroll")                                                      \
      for (int q = 0; q < 2; q++) {                                          \
        int dw = bk * 128 + ((bn0 + q * 4) ^ bswz);                          \
        cpa16(sb + ((st) * BSTAGE + dw) * 4, srcB + q * 4, bytes);           \
      }                                                                      \
    }                                                                        \
    cp_commit();                                                             \
  }

template<int ACT>
__global__ void __launch_bounds__(256, 2)
gemm_merged(GP Pa, GP Pb, int nblkA)
{
    __shared__ __align__(16) float As[2][ASTAGE];
    __shared__ __align__(16) float Bs[2][BSTAGE];

    const GP P = (blockIdx.x < (unsigned)nblkA) ? Pa : Pb;
    const int b = (blockIdx.x < (unsigned)nblkA) ? blockIdx.x : blockIdx.x - nblkA;
    const int mb = b % 28;
    const int r_ = b / 28;
    const int nb = r_ % P.nN;
    const int sk = r_ / P.nN;

    const int tid  = threadIdx.x;
    const int lane = tid & 31;
    const int warp = tid >> 5;
    const int bm = mb * 128;
    const int bn = nb * 128;
    const int wm = (warp & 3) * 32;
    const int wn = (warp >> 2) * 64;
    const int kbeg = sk * P.Kchunk;
    const int kend = min(kbeg + P.Kchunk, P.Ktot);

    // A loader: thread t -> row t>>1, k-half (t&1)*8
    const int am = tid >> 1;
    const int arow = bm + am;
    const bool aval = arow < P.M;
    const float* Aptr;
    {
        int r0 = aval ? arow : 0;
        Aptr = (r0 < P.n_r) ? (P.A0 + (size_t)r0 * P.Ktot)
                            : (P.A1 + (size_t)(r0 - P.n_r) * P.Ktot);
    }
    const int akoff  = (tid & 1) * 8;
    const int ambase = am * 16;
    const int awz    = ((am >> 1) & 3) << 2;
    const uint32_t sa = sptr(&As[0][0]);

    // B loader: thread t -> k row t>>4, n block (t&15)*8
    const int bk   = tid >> 4;
    const int bn0  = (tid & 15) * 8;
    const int bswz = (bk & 3) << 3;
    const uint32_t sb = sptr(&Bs[0][0]);

    float acc[2][8][4];
#pragma unroll
    for (int i = 0; i < 2; i++)
#pragma unroll
        for (int j = 0; j < 8; j++)
#pragma unroll
            for (int q = 0; q < 4; q++) acc[i][j][q] = 0.f;

    const int fr = lane >> 2;
    const int fc = lane & 3;
    const int nT = (kend - kbeg + 15) >> 4;

    GEMM_LOAD(0, kbeg)

    for (int t = 0; t < nT; t++) {
        if (t + 1 < nT) {
            GEMM_LOAD((t + 1) & 1, kbeg + (t + 1) * 16)
        } else {
            cp_commit();
        }
        cp_wait1();
        __syncthreads();

        const float* as = &As[t & 1][0];
        const float* bs = &Bs[t & 1][0];
#pragma unroll
        for (int kq = 0; kq < 2; kq++) {
            uint32_t af[2][4], bf[8][2];
#pragma unroll
            for (int i = 0; i < 2; i++) {
                const int row = wm + i * 16 + fr;
                const int swz = ((row >> 1) & 3) << 2;
                const float* p  = as + row * 16;
                const float* p8 = as + (row + 8) * 16;
                const int c0 = (fc + kq * 8) ^ swz;
                const int c4 = (fc + 4 + kq * 8) ^ swz;
                af[i][0] = __float_as_uint(p[c0]);
                af[i][1] = __float_as_uint(p8[c0]);
                af[i][2] = __float_as_uint(p[c4]);
                af[i][3] = __float_as_uint(p8[c4]);
            }
#pragma unroll
            for (int j = 0; j < 8; j++) {
                const int n = (wn + j * 8 + fr) ^ (fc << 3);
                bf[j][0] = __float_as_uint(bs[(fc + kq * 8) * 128 + n]);
                bf[j][1] = __float_as_uint(bs[(fc + 4 + kq * 8) * 128 + n]);
            }
#pragma unroll
            for (int i = 0; i < 2; i++)
#pragma unroll
                for (int j = 0; j < 8; j++)
                    mma_tf32(acc[i][j], af[i], bf[j]);
        }
        __syncthreads();
    }

    // epilogue
    float* Cb = P.C;
    if (ACT == 2) Cb += (size_t)sk * P.M * P.N;
#pragma unroll
    for (int i = 0; i < 2; i++) {
        const int m0 = bm + wm + i * 16 + fr;
#pragma unroll
        for (int j = 0; j < 8; j++) {
            const int n0 = bn + wn + j * 8 + fc * 2;
            float b0 = 0.f, b1 = 0.f;
            if (ACT == 0) { b0 = P.bias[n0]; b1 = P.bias[n0 + 1]; }
            if (m0 < P.M) {
                float v0 = acc[i][j][0] + b0, v1 = acc[i][j][1] + b1;
                if (ACT == 0) { v0 = gelu_exact(v0); v1 = gelu_exact(v1); }
                Cb[(size_t)m0 * P.N + n0]     = v0;
                Cb[(size_t)m0 * P.N + n0 + 1] = v1;
            }
            if (m0 + 8 < P.M) {
                float v2 = acc[i][j][2] + b0, v3 = acc[i][j][3] + b1;
                if (ACT == 0) { v2 = gelu_exact(v2); v3 = gelu_exact(v3); }
                Cb[(size_t)(m0 + 8) * P.N + n0]     = v2;
                Cb[(size_t)(m0 + 8) * P.N + n0 + 1] = v3;
            }
        }
    }
}

// ---------------- layer-2 split-K reduce + bias + sigmoid + scatter ----------------
__global__ void __launch_bounds__(256)
l2_epilogue(const float* __restrict__ pa, const float* __restrict__ pf,
            const float* __restrict__ ba, const float* __restrict__ bf,
            float* __restrict__ d_out)
{
    int t = blockIdx.x * blockDim.x + threadIdx.x;
    if (t >= NM * 128) return;
    int m  = t >> 7;
    int c4 = (t & 127) * 4;
    const float* src;
    const float* bb;
    int c;
    if (c4 < 256) { src = pa + (size_t)m * 256 + c4;         bb = ba; c = c4; }
    else          { src = pf + (size_t)m * 256 + (c4 - 256); bb = bf; c = c4 - 256; }
    float v[4];
#pragma unroll
    for (int q = 0; q < 4; q++) {
        float s = bb[c + q];
#pragma unroll
        for (int sk = 0; sk < SPLITK; sk++)
            s += src[(size_t)sk * NM * 256 + q];
        v[q] = 1.f / (1.f + expf(-s));
    }
    size_t dst = (m < NR) ? ((size_t)m * 512 + c4)
                          : (E_P_OFS + (size_t)(m - NR) * 512 + c4);
    *(float4*)(d_out + dst) = make_float4(v[0], v[1], v[2], v[3]);
}

// ---------------- fused gather + conv1/pool + conv2(f32x2)/pool + tanh + out GEMV ----------------
__global__ void __launch_bounds__(256)
conv_kernel(const int* __restrict__ idx, const float* __restrict__ W_out,
            float* __restrict__ d_out)
{
    __shared__ float xp[2][516];        // input rows with halo (index iw+2)
    __shared__ float h1p[16][2][260];   // pooled conv1 with halo (index pw+2)
    __shared__ float red[16];

    const int s = blockIdx.x;
    const int tid = threadIdx.x;
    const int w = tid >> 5, l = tid & 31;

    const int id = idx[s];
    const int r_no = id / 1512;
    const int p_no = id % 1512;
    const float* er = d_out + (size_t)r_no * 512;
    const float* ep = d_out + E_P_OFS + (size_t)p_no * 512;

    for (int t = tid; t < 2 * 516; t += 256) {
        int row = (t >= 516);
        int c = row ? (t - 516) : t;
        int iw = c - 2;
        float v = 0.f;
        if (iw >= 0 && iw < 512) v = row ? ep[iw] : er[iw];
        xp[row][c] = v;
    }
    if (tid < 128) {
        int ic = tid >> 3, rem = tid & 7;
        int ih = rem >> 2, e = rem & 3;
        int c = (e < 2) ? e : (256 + e);
        h1p[ic][ih][c] = 0.f;
    }
    __syncthreads();

    // ---- conv1 (3x5, pad 2) + leaky + avgpool(2x2) ----
#pragma unroll
    for (int ph = 0; ph < 2; ph++) {
#pragma unroll
        for (int j = 0; j < 8; j++) {
            int pw = l + 32 * j;
            float t0[6], t1[6];
#pragma unroll
            for (int q = 0; q < 6; q++) { t0[q] = xp[0][2 * pw + q]; t1[q] = xp[1][2 * pw + q]; }
#pragma unroll
            for (int oi = 0; oi < 2; oi++) {
                int oc = w + 8 * oi;
                float b = c_b1[oc];
                float v00 = b, v01 = b, v10 = b, v11 = b;
#pragma unroll
                for (int kw = 0; kw < 5; kw++) {
                    float w0 = c_w1[oc * 15 + 0 + kw];
                    float w1 = c_w1[oc * 15 + 5 + kw];
                    float w2 = c_w1[oc * 15 + 10 + kw];
                    if (ph == 0) {
                        v00 += t0[kw] * w2;                 v01 += t0[kw + 1] * w2;
                        v10 += t0[kw] * w1 + t1[kw] * w2;   v11 += t0[kw + 1] * w1 + t1[kw + 1] * w2;
                    } else {
                        v00 += t0[kw] * w0 + t1[kw] * w1;   v01 += t0[kw + 1] * w0 + t1[kw + 1] * w1;
                        v10 += t1[kw] * w0;                 v11 += t1[kw + 1] * w0;
                    }
                }
                float lk00 = v00 >= 0.f ? v00 : 0.01f * v00;
                float lk01 = v01 >= 0.f ? v01 : 0.01f * v01;
                float lk10 = v10 >= 0.f ? v10 : 0.01f * v10;
                float lk11 = v11 >= 0.f ? v11 : 0.01f * v11;
                h1p[oc][ph][pw + 2] = 0.25f * (lk00 + lk01 + lk10 + lk11);
            }
        }
    }
    __syncthreads();

    // ---- conv2 (packed f32x2) + leaky + maxpool + tanh + out dot ----
    float p0 = 0.f, p1 = 0.f;
#pragma unroll 1
    for (int oig = 0; oig < 2; oig++) {
        ull accp[2][4][4];
#pragma unroll
        for (int a = 0; a < 2; a++) {
            float b = c_b2[w + 8 * a + 16 * oig];
            ull bp = packf2(b, b);
#pragma unroll
            for (int oh = 0; oh < 4; oh++)
#pragma unroll
                for (int jp = 0; jp < 4; jp++) accp[a][oh][jp] = bp;
        }
#pragma unroll 1
        for (int ic = 0; ic < 16; ic++) {
            ull wgp[2][15];
#pragma unroll
            for (int a = 0; a < 2; a++) {
                int oc = w + 8 * a + 16 * oig;
                const float* cw = c_w2 + ((size_t)oc * 16 + ic) * 15;
#pragma unroll
                for (int q = 0; q < 15; q++) { float c = cw[q]; wgp[a][q] = packf2(c, c); }
            }
#pragma unroll
            for (int jp = 0; jp < 4; jp++) {
                int owA = l + 32 * jp;
                int owB = owA + 128;
                ull pu0[5], pu1[5];
#pragma unroll
                for (int q = 0; q < 5; q++) {
                    pu0[q] = packf2(h1p[ic][0][owA + q], h1p[ic][0][owB + q]);
                    pu1[q] = packf2(h1p[ic][1][owA + q], h1p[ic][1][owB + q]);
                }
#pragma unroll
                for (int a = 0; a < 2; a++) {
#pragma unroll
                    for (int kw = 0; kw < 5; kw++) {
                        ull w0 = wgp[a][kw], w1 = wgp[a][5 + kw], w2 = wgp[a][10 + kw];
                        ffma2(accp[a][0][jp], pu0[kw], w2);
                        ffma2(accp[a][1][jp], pu0[kw], w1);
                        ffma2(accp[a][1][jp], pu1[kw], w2);
                        ffma2(accp[a][2][jp], pu0[kw], w0);
                        ffma2(accp[a][2][jp], pu1[kw], w1);
                        ffma2(accp[a][3][jp], pu1[kw], w0);
                    }
                }
            }
        }
#pragma unroll
        for (int a = 0; a < 2; a++) {
            int oc = w + 8 * a + 16 * oig;
#pragma unroll
            for (int ph = 0; ph < 2; ph++) {
#pragma unroll
                for (int jp = 0; jp < 4; jp++) {
                    float lo0, hi0, lo1, hi1;
                    unpackf2(accp[a][2 * ph][jp],     lo0, hi0);
                    unpackf2(accp[a][2 * ph + 1][jp], lo1, hi1);
#pragma unroll
                    for (int half = 0; half < 2; half++) {
                        int j = jp + 4 * half;
                        float m = half ? fmaxf(hi0, hi1) : fmaxf(lo0, lo1);
                        float o = __shfl_xor_sync(0xffffffffu, m, 1);
                        m = fmaxf(m, o);
                        if ((l & 1) == 0) {
                            float lv = m >= 0.f ? m : 0.01f * m;
                            float val = tanhf(lv);
                            int pw = (l >> 1) + 16 * j;
                            int fidx = oc * 256 + ph * 128 + pw;
                            d_out[FLAT_OFS + (size_t)s * 8192 + fidx] = val;
                            p0 += val * __ldg(W_out + 2 * fidx);
                            p1 += val * __ldg(W_out + 2 * fidx + 1);
                        }
                    }
                }
            }
        }
    }

#pragma unroll
    for (int off = 16; off > 0; off >>= 1) {
        p0 += __shfl_xor_sync(0xffffffffu, p0, off);
        p1 += __shfl_xor_sync(0xffffffffu, p1, off);
    }
    if (l == 0) { red[w] = p0; red[8 + w] = p1; }
    __syncthreads();
    if (tid == 0) {
        float s0 = c_bout[0], s1 = c_bout[1];
#pragma unroll
        for (int q = 0; q < 8; q++) { s0 += red[q]; s1 += red[8 + q]; }
        d_out[OUT_OFS + 2 * (size_t)s]     = s0;
        d_out[OUT_OFS + 2 * (size_t)s + 1] = s1;
    }
}

// ---------------- launch ----------------
extern "C" void kernel_launch(void* const* d_in, const int* in_sizes, int n_in,
                              void* d_out_, int out_size)
{
    (void)in_sizes; (void)n_in; (void)out_size;
    const float* r_att  = (const float*)d_in[0];
    const float* p_att  = (const float*)d_in[1];
    const float* r_fun  = (const float*)d_in[2];
    const float* p_fun  = (const float*)d_in[3];
    const int*   idx    = (const int*)d_in[4];
    const float* W_att1 = (const float*)d_in[5];
    const float* b_att1 = (const float*)d_in[6];
    const float* W_att2 = (const float*)d_in[7];
    const float* b_att2 = (const float*)d_in[8];
    const float* W_fun1 = (const float*)d_in[9];
    const float* b_fun1 = (const float*)d_in[10];
    const float* W_fun2 = (const float*)d_in[11];
    const float* b_fun2 = (const float*)d_in[12];
    const float* W_out  = (const float*)d_in[17];
    float* d_out = (float*)d_out_;

    cudaMemcpyToSymbolAsync(c_w1,   d_in[13], 240  * sizeof(float), 0, cudaMemcpyDeviceToDevice);
    cudaMemcpyToSymbolAsync(c_b1,   d_in[14], 16   * sizeof(float), 0, cudaMemcpyDeviceToDevice);
    cudaMemcpyToSymbolAsync(c_w2,   d_in[15], 7680 * sizeof(float), 0, cudaMemcpyDeviceToDevice);
    cudaMemcpyToSymbolAsync(c_b2,   d_in[16], 32   * sizeof(float), 0, cudaMemcpyDeviceToDevice);
    cudaMemcpyToSymbolAsync(c_bout, d_in[18], 2    * sizeof(float), 0, cudaMemcpyDeviceToDevice);

    float *h_att_p = 0, *h_fun_p = 0, *pa = 0, *pf = 0;
    cudaGetSymbolAddress((void**)&h_att_p, g_h_att);
    cudaGetSymbolAddress((void**)&h_fun_p, g_h_fun);
    cudaGetSymbolAddress((void**)&pa, g_part_att);
    cudaGetSymbolAddress((void**)&pf, g_part_fun);

    // layer-1 merged: fun first (longest-job-first), att second.
    GP Pfun1 = { r_fun, p_fun, W_fun1, b_fun1, h_fun_p,
                 NR, NM, 4096, 5603, 5603, 32, 0 };
    GP Patt1 = { r_att, p_att, W_att1, b_att1, h_att_p,
                 NR, NM, 2048, 3000, 3000, 16, 1 };
    // layer-2 merged split-K partials.
    GP Pfun2 = { h_fun_p, h_fun_p, W_fun2, b_fun2, pf,
                 NM, NM, 256, 4096, 4096 / SPLITK, 2, 1 };
    GP Patt2 = { h_att_p, h_att_p, W_att2, b_att2, pa,
                 NM, NM, 256, 2048, 2048 / SPLITK, 2, 1 };

    const int nblk_fun1 = 28 * 32;            // 896
    const int nblk_att1 = 28 * 16;            // 448
    const int nblk_l2   = 28 * 2 * SPLITK;    // 224 each

    dim3 blk(256);
    gemm_merged<0><<<nblk_fun1 + nblk_att1, blk>>>(Pfun1, Patt1, nblk_fun1);
    gemm_merged<2><<<2 * nblk_l2, blk>>>(Pfun2, Patt2, nblk_l2);
    // reduce + bias + sigmoid + scatter to e_r / e_p
    l2_epilogue<<<(NM * 128 + 255) / 256, 256>>>(pa, pf, b_att2, b_fun2, d_out);
    // conv stage
    conv_kernel<<<NSAMP, blk>>>(idx, W_out, d_out);
}

// round 14
// speedup vs baseline: 1.4977x; 1.4132x over previous
#include <cuda_runtime.h>
#include <cuda_fp16.h>
#include <math.h>
#include <stdint.h>

// ---------------- problem constants ----------------
#define NR 2000
#define NP 1512
#define NM 3512            // NR + NP
#define NSAMP 8192
#define SPLITK 4

#define E_P_OFS  ((size_t)NR * 512)                 // 1,024,000
#define OUT_OFS  (E_P_OFS + (size_t)NP * 512)       // 1,798,144
#define FLAT_OFS (OUT_OFS + (size_t)NSAMP * 2)      // 1,814,528

// padded K (fp16 elems, multiples of 32)
#define KA_ATT 3008        // 94 tiles
#define KA_FUN 5632        // 176 tiles
#define NT_ATT1 94
#define NT_FUN1 176

typedef unsigned long long ull;

// ---------------- scratch (no allocations allowed) ----------------
__device__ __align__(16) __half g_a_att[(size_t)NM * KA_ATT];
__device__ __align__(16) __half g_a_fun[(size_t)NM * KA_FUN];
__device__ __align__(16) __half g_h_att[(size_t)NM * 2048];
__device__ __align__(16) __half g_h_fun[(size_t)NM * 4096];
__device__ __align__(16) uint32_t g_w_att1[(size_t)NT_ATT1 * 16 * 2048];
__device__ __align__(16) uint32_t g_w_fun1[(size_t)NT_FUN1 * 16 * 4096];
__device__ __align__(16) uint32_t g_w_att2[(size_t)64 * 16 * 256];
__device__ __align__(16) uint32_t g_w_fun2[(size_t)128 * 16 * 256];
__device__ float g_part_att[(size_t)SPLITK * NM * 256];
__device__ float g_part_fun[(size_t)SPLITK * NM * 256];

// conv weights/biases in constant memory
__constant__ float c_w1[240];    // [16][3][5]
__constant__ float c_b1[16];
__constant__ float c_w2[7680];   // [32][16][3][5]
__constant__ float c_b2[32];
__constant__ float c_bout[2];

__device__ __forceinline__ float gelu_exact(float x) {
    return 0.5f * x * (1.0f + erff(x * 0.70710678118654752440f));
}

// ---------------- packed f32x2 helpers (sm_103a) ----------------
__device__ __forceinline__ ull packf2(float lo, float hi) {
    ull r; asm("mov.b64 %0, {%1,%2};" : "=l"(r) : "f"(lo), "f"(hi)); return r;
}
__device__ __forceinline__ void unpackf2(ull v, float& lo, float& hi) {
    asm("mov.b64 {%0,%1}, %2;" : "=f"(lo), "=f"(hi) : "l"(v));
}
__device__ __forceinline__ void ffma2(ull& d, ull a, ull b) {
    asm("fma.rn.f32x2 %0, %1, %2, %0;" : "+l"(d) : "l"(a), "l"(b));
}

// ---------------- async copy + mma helpers ----------------
__device__ __forceinline__ uint32_t sptr(const void* p) {
    return (uint32_t)__cvta_generic_to_shared(p);
}
__device__ __forceinline__ void cpa16(uint32_t d, const void* s, int bytes) {
    asm volatile("cp.async.cg.shared.global [%0], [%1], 16, %2;\n"
                 :: "r"(d), "l"(s), "r"(bytes));
}
__device__ __forceinline__ void cp_commit() {
    asm volatile("cp.async.commit_group;\n");
}
__device__ __forceinline__ void cp_wait1() {
    asm volatile("cp.async.wait_group 1;\n" ::: "memory");
}
// fp16 mma m16n8k16, fp32 accumulate
__device__ __forceinline__ void mma_fp16(float* d, const uint32_t* a, const uint32_t* b) {
    asm volatile(
        "mma.sync.aligned.m16n8k16.row.col.f32.f16.f16.f32 "
        "{%0,%1,%2,%3}, {%4,%5,%6,%7}, {%8,%9}, {%0,%1,%2,%3};\n"
        : "+f"(d[0]), "+f"(d[1]), "+f"(d[2]), "+f"(d[3])
        : "r"(a[0]), "r"(a[1]), "r"(a[2]), "r"(a[3]), "r"(b[0]), "r"(b[1]));
}

// ---------------- pre-pass: fp32 -> fp16 converts ----------------
// A: concat (src0 rows [0,n_r), src1 rows [n_r,M)) -> dst[M][Kpad] fp16, pad zeroed.
__global__ void __launch_bounds__(256)
cvtA(const float* __restrict__ s0, const float* __restrict__ s1, int n_r,
     int K, int Kpad, __half* __restrict__ dst, int M)
{
    long long u = (long long)blockIdx.x * 256 + threadIdx.x;
    int pairs = Kpad >> 1;
    if (u >= (long long)M * pairs) return;
    int row = (int)(u / pairs);
    int k = (int)(u % pairs) * 2;
    const float* s = (row < n_r) ? (s0 + (size_t)row * K)
                                 : (s1 + (size_t)(row - n_r) * K);
    float v0 = (k     < K) ? s[k]     : 0.f;
    float v1 = (k + 1 < K) ? s[k + 1] : 0.f;
    ((__half2*)dst)[u] = __floats2half2_rn(v0, v1);
}

// W[K][N] fp32 -> Wp[k'][N] b32 where word = (W[2k'][n], W[2k'+1][n]) fp16 pair.
__global__ void __launch_bounds__(256)
cvtW(const float* __restrict__ W, int K, int N, int rowsOut,
     uint32_t* __restrict__ dst)
{
    long long u = (long long)blockIdx.x * 256 + threadIdx.x;
    if (u >= (long long)rowsOut * N) return;
    int kp = (int)(u / N);
    int n  = (int)(u % N);
    int k = kp * 2;
    float v0 = (k     < K) ? W[(size_t)k * N + n]       : 0.f;
    float v1 = (k + 1 < K) ? W[(size_t)(k + 1) * N + n] : 0.f;
    __half2 h = __floats2half2_rn(v0, v1);
    dst[u] = *(uint32_t*)&h;
}

// ---------------- fp16 tensor-core GEMM (merged 2 problems / launch) ----------------
// BM=128, BN=128, BK=32 (2 x k16 mma steps). 256 thr = 8 warps (4m x 2n), warp 32x64.
// A smem: [m][16 words], word c ^= ((m>>1)&3)<<2.  B smem: [k'][128 words], n ^= (k'&3)<<3.
// ACT==0: bias+gelu -> fp16 C[M][N].  ACT==2: raw fp32 partial -> C + sk*M*N.
// block decode: mb = b%28 ; r = b/28 ; nb = r%nN ; sk = r/nN.  kt tiles = [sk*chunkT, +chunkT)
struct GP {
    const __half* A; const uint32_t* Wp; const float* bias; void* C;
    int M, N, strideA, chunkT, nN;
};

#define GLOAD(st, kt)                                                          \
  {                                                                            \
    {                                                                          \
      const __half* srcA = Aptr + (size_t)(kt) * 32 + aw0 * 2;                 \
      int ab = aval ? 16 : 0;                                                  \
      cpa16(sa + ((st) * 2048 + am * 16 + ((aw0)     ^ awz)) * 4, srcA,     ab); \
      cpa16(sa + ((st) * 2048 + am * 16 + ((aw0 + 4) ^ awz)) * 4, srcA + 8, ab); \
    }                                                                          \
    {                                                                          \
      const uint32_t* srcB = P.Wp + (size_t)((kt) * 16 + bkr) * P.N + bn + bn0;\
      cpa16(sb + ((st) * 2048 + bkr * 128 + ((bn0)     ^ bswz)) * 4, srcB,     16); \
      cpa16(sb + ((st) * 2048 + bkr * 128 + ((bn0 + 4) ^ bswz)) * 4, srcB + 4, 16); \
    }                                                                          \
    cp_commit();                                                               \
  }

template<int ACT>
__global__ void __launch_bounds__(256, 2)
gemm_fp16(GP Pa, GP Pb, int nblkA)
{
    __shared__ __align__(16) uint32_t As[2][128 * 16];
    __shared__ __align__(16) uint32_t Bs[2][16 * 128];

    const GP P = (blockIdx.x < (unsigned)nblkA) ? Pa : Pb;
    const int b = (blockIdx.x < (unsigned)nblkA) ? blockIdx.x : blockIdx.x - nblkA;
    const int mb = b % 28;
    const int r_ = b / 28;
    const int nb = r_ % P.nN;
    const int sk = r_ / P.nN;

    const int tid  = threadIdx.x;
    const int lane = tid & 31;
    const int warp = tid >> 5;
    const int bm = mb * 128;
    const int bn = nb * 128;
    const int wm = (warp & 3) * 32;
    const int wn = (warp >> 2) * 64;
    const int tbeg = sk * P.chunkT;

    // A loader: row am = tid>>1, word-half aw0 = (tid&1)*8
    const int am = tid >> 1;
    const int arow = bm + am;
    const bool aval = arow < P.M;
    const __half* Aptr = P.A + (size_t)(aval ? arow : 0) * P.strideA;
    const int aw0 = (tid & 1) * 8;
    const int awz = ((am >> 1) & 3) << 2;
    const uint32_t sa = sptr(&As[0][0]);

    // B loader: k'-row bkr = tid>>4 (0..15), word block bn0 = (tid&15)*8
    const int bkr  = tid >> 4;
    const int bn0  = (tid & 15) * 8;
    const int bswz = (bkr & 3) << 3;
    const uint32_t sb = sptr(&Bs[0][0]);

    float acc[2][8][4];
#pragma unroll
    for (int i = 0; i < 2; i++)
#pragma unroll
        for (int j = 0; j < 8; j++)
#pragma unroll
            for (int q = 0; q < 4; q++) acc[i][j][q] = 0.f;

    const int fr = lane >> 2;
    const int fc = lane & 3;
    const int nT = P.chunkT;

    GLOAD(0, tbeg)

    for (int t = 0; t < nT; t++) {
        if (t + 1 < nT) {
            GLOAD((t + 1) & 1, tbeg + t + 1)
        } else {
            cp_commit();
        }
        cp_wait1();
        __syncthreads();

        const uint32_t* as = &As[t & 1][0];
        const uint32_t* bs = &Bs[t & 1][0];
#pragma unroll
        for (int kq = 0; kq < 2; kq++) {
            uint32_t af[2][4], bf[8][2];
#pragma unroll
            for (int i = 0; i < 2; i++) {
                const int row = wm + i * 16 + fr;
                const int swz = ((row >> 1) & 3) << 2;
                const uint32_t* p  = as + row * 16;
                const uint32_t* p8 = as + (row + 8) * 16;
                const int c0 = (kq * 8 + fc)     ^ swz;
                const int c4 = (kq * 8 + fc + 4) ^ swz;
                af[i][0] = p[c0];
                af[i][1] = p8[c0];
                af[i][2] = p[c4];
                af[i][3] = p8[c4];
            }
#pragma unroll
            for (int j = 0; j < 8; j++) {
                const int n = (wn + j * 8 + fr) ^ (fc << 3);
                bf[j][0] = bs[(kq * 8 + fc)     * 128 + n];
                bf[j][1] = bs[(kq * 8 + fc + 4) * 128 + n];
            }
#pragma unroll
            for (int i = 0; i < 2; i++)
#pragma unroll
                for (int j = 0; j < 8; j++)
                    mma_fp16(acc[i][j], af[i], bf[j]);
        }
        __syncthreads();
    }

    // epilogue
#pragma unroll
    for (int i = 0; i < 2; i++) {
        const int m0 = bm + wm + i * 16 + fr;
#pragma unroll
        for (int j = 0; j < 8; j++) {
            const int n0 = bn + wn + j * 8 + fc * 2;
            if (ACT == 0) {
                __half* Ch = (__half*)P.C;
                float b0 = P.bias[n0], b1 = P.bias[n0 + 1];
                if (m0 < P.M) {
                    float v0 = gelu_exact(acc[i][j][0] + b0);
                    float v1 = gelu_exact(acc[i][j][1] + b1);
                    *(__half2*)(Ch + (size_t)m0 * P.N + n0) = __floats2half2_rn(v0, v1);
                }
                if (m0 + 8 < P.M) {
                    float v2 = gelu_exact(acc[i][j][2] + b0);
                    float v3 = gelu_exact(acc[i][j][3] + b1);
                    *(__half2*)(Ch + (size_t)(m0 + 8) * P.N + n0) = __floats2half2_rn(v2, v3);
                }
            } else {
                float* Cf = (float*)P.C + (size_t)sk * P.M * P.N;
                if (m0 < P.M) {
                    Cf[(size_t)m0 * P.N + n0]     = acc[i][j][0];
                    Cf[(size_t)m0 * P.N + n0 + 1] = acc[i][j][1];
                }
                if (m0 + 8 < P.M) {
                    Cf[(size_t)(m0 + 8) * P.N + n0]     = acc[i][j][2];
                    Cf[(size_t)(m0 + 8) * P.N + n0 + 1] = acc[i][j][3];
                }
            }
        }
    }
}

// ---------------- layer-2 split-K reduce + bias + sigmoid + scatter ----------------
__global__ void __launch_bounds__(256)
l2_epilogue(const float* __restrict__ pa, const float* __restrict__ pf,
            const float* __restrict__ ba, const float* __restrict__ bf,
            float* __restrict__ d_out)
{
    int t = blockIdx.x * blockDim.x + threadIdx.x;
    if (t >= NM * 128) return;
    int m  = t >> 7;
    int c4 = (t & 127) * 4;
    const float* src;
    const float* bb;
    int c;
    if (c4 < 256) { src = pa + (size_t)m * 256 + c4;         bb = ba; c = c4; }
    else          { src = pf + (size_t)m * 256 + (c4 - 256); bb = bf; c = c4 - 256; }
    float v[4];
#pragma unroll
    for (int q = 0; q < 4; q++) {
        float s = bb[c + q];
#pragma unroll
        for (int sk = 0; sk < SPLITK; sk++)
            s += src[(size_t)sk * NM * 256 + q];
        v[q] = 1.f / (1.f + expf(-s));
    }
    size_t dst = (m < NR) ? ((size_t)m * 512 + c4)
                          : (E_P_OFS + (size_t)(m - NR) * 512 + c4);
    *(float4*)(d_out + dst) = make_float4(v[0], v[1], v[2], v[3]);
}

// ---------------- fused gather + conv1/pool + conv2(f32x2)/pool + tanh + out GEMV ----------------
__global__ void __launch_bounds__(256)
conv_kernel(const int* __restrict__ idx, const float* __restrict__ W_out,
            float* __restrict__ d_out)
{
    __shared__ float xp[2][516];
    __shared__ float h1p[16][2][260];
    __shared__ float red[16];

    const int s = blockIdx.x;
    const int tid = threadIdx.x;
    const int w = tid >> 5, l = tid & 31;

    const int id = idx[s];
    const int r_no = id / 1512;
    const int p_no = id % 1512;
    const float* er = d_out + (size_t)r_no * 512;
    const float* ep = d_out + E_P_OFS + (size_t)p_no * 512;

    for (int t = tid; t < 2 * 516; t += 256) {
        int row = (t >= 516);
        int c = row ? (t - 516) : t;
        int iw = c - 2;
        float v = 0.f;
        if (iw >= 0 && iw < 512) v = row ? ep[iw] : er[iw];
        xp[row][c] = v;
    }
    if (tid < 128) {
        int ic = tid >> 3, rem = tid & 7;
        int ih = rem >> 2, e = rem & 3;
        int c = (e < 2) ? e : (256 + e);
        h1p[ic][ih][c] = 0.f;
    }
    __syncthreads();

#pragma unroll
    for (int ph = 0; ph < 2; ph++) {
#pragma unroll
        for (int j = 0; j < 8; j++) {
            int pw = l + 32 * j;
            float t0[6], t1[6];
#pragma unroll
            for (int q = 0; q < 6; q++) { t0[q] = xp[0][2 * pw + q]; t1[q] = xp[1][2 * pw + q]; }
#pragma unroll
            for (int oi = 0; oi < 2; oi++) {
                int oc = w + 8 * oi;
                float b = c_b1[oc];
                float v00 = b, v01 = b, v10 = b, v11 = b;
#pragma unroll
                for (int kw = 0; kw < 5; kw++) {
                    float w0 = c_w1[oc * 15 + 0 + kw];
                    float w1 = c_w1[oc * 15 + 5 + kw];
                    float w2 = c_w1[oc * 15 + 10 + kw];
                    if (ph == 0) {
                        v00 += t0[kw] * w2;                 v01 += t0[kw + 1] * w2;
                        v10 += t0[kw] * w1 + t1[kw] * w2;   v11 += t0[kw + 1] * w1 + t1[kw + 1] * w2;
                    } else {
                        v00 += t0[kw] * w0 + t1[kw] * w1;   v01 += t0[kw + 1] * w0 + t1[kw + 1] * w1;
                        v10 += t1[kw] * w0;                 v11 += t1[kw + 1] * w0;
                    }
                }
                float lk00 = v00 >= 0.f ? v00 : 0.01f * v00;
                float lk01 = v01 >= 0.f ? v01 : 0.01f * v01;
                float lk10 = v10 >= 0.f ? v10 : 0.01f * v10;
                float lk11 = v11 >= 0.f ? v11 : 0.01f * v11;
                h1p[oc][ph][pw + 2] = 0.25f * (lk00 + lk01 + lk10 + lk11);
            }
        }
    }
    __syncthreads();

    float p0 = 0.f, p1 = 0.f;
#pragma unroll 1
    for (int oig = 0; oig < 2; oig++) {
        ull accp[2][4][4];
#pragma unroll
        for (int a = 0; a < 2; a++) {
            float b = c_b2[w + 8 * a + 16 * oig];
            ull bp = packf2(b, b);
#pragma unroll
            for (int oh = 0; oh < 4; oh++)
#pragma unroll
                for (int jp = 0; jp < 4; jp++) accp[a][oh][jp] = bp;
        }
#pragma unroll 1
        for (int ic = 0; ic < 16; ic++) {
            ull wgp[2][15];
#pragma unroll
            for (int a = 0; a < 2; a++) {
                int oc = w + 8 * a + 16 * oig;
                const float* cw = c_w2 + ((size_t)oc * 16 + ic) * 15;
#pragma unroll
                for (int q = 0; q < 15; q++) { float c = cw[q]; wgp[a][q] = packf2(c, c); }
            }
#pragma unroll
            for (int jp = 0; jp < 4; jp++) {
                int owA = l + 32 * jp;
                int owB = owA + 128;
                ull pu0[5], pu1[5];
#pragma unroll
                for (int q = 0; q < 5; q++) {
                    pu0[q] = packf2(h1p[ic][0][owA + q], h1p[ic][0][owB + q]);
                    pu1[q] = packf2(h1p[ic][1][owA + q], h1p[ic][1][owB + q]);
                }
#pragma unroll
                for (int a = 0; a < 2; a++) {
#pragma unroll
                    for (int kw = 0; kw < 5; kw++) {
                        ull w0 = wgp[a][kw], w1 = wgp[a][5 + kw], w2 = wgp[a][10 + kw];
                        ffma2(accp[a][0][jp], pu0[kw], w2);
                        ffma2(accp[a][1][jp], pu0[kw], w1);
                        ffma2(accp[a][1][jp], pu1[kw], w2);
                        ffma2(accp[a][2][jp], pu0[kw], w0);
                        ffma2(accp[a][2][jp], pu1[kw], w1);
                        ffma2(accp[a][3][jp], pu1[kw], w0);
                    }
                }
            }
        }
#pragma unroll
        for (int a = 0; a < 2; a++) {
            int oc = w + 8 * a + 16 * oig;
#pragma unroll
            for (int ph = 0; ph < 2; ph++) {
#pragma unroll
                for (int jp = 0; jp < 4; jp++) {
                    float lo0, hi0, lo1, hi1;
                    unpackf2(accp[a][2 * ph][jp],     lo0, hi0);
                    unpackf2(accp[a][2 * ph + 1][jp], lo1, hi1);
#pragma unroll
                    for (int half = 0; half < 2; half++) {
                        int j = jp + 4 * half;
                        float m = half ? fmaxf(hi0, hi1) : fmaxf(lo0, lo1);
                        float o = __shfl_xor_sync(0xffffffffu, m, 1);
                        m = fmaxf(m, o);
                        if ((l & 1) == 0) {
                            float lv = m >= 0.f ? m : 0.01f * m;
                            float val = tanhf(lv);
                            int pw = (l >> 1) + 16 * j;
                            int fidx = oc * 256 + ph * 128 + pw;
                            d_out[FLAT_OFS + (size_t)s * 8192 + fidx] = val;
                            p0 += val * __ldg(W_out + 2 * fidx);
                            p1 += val * __ldg(W_out + 2 * fidx + 1);
                        }
                    }
                }
            }
        }
    }

#pragma unroll
    for (int off = 16; off > 0; off >>= 1) {
        p0 += __shfl_xor_sync(0xffffffffu, p0, off);
        p1 += __shfl_xor_sync(0xffffffffu, p1, off);
    }
    if (l == 0) { red[w] = p0; red[8 + w] = p1; }
    __syncthreads();
    if (tid == 0) {
        float s0 = c_bout[0], s1 = c_bout[1];
#pragma unroll
        for (int q = 0; q < 8; q++) { s0 += red[q]; s1 += red[8 + q]; }
        d_out[OUT_OFS + 2 * (size_t)s]     = s0;
        d_out[OUT_OFS + 2 * (size_t)s + 1] = s1;
    }
}

// ---------------- launch ----------------
extern "C" void kernel_launch(void* const* d_in, const int* in_sizes, int n_in,
                              void* d_out_, int out_size)
{
    (void)in_sizes; (void)n_in; (void)out_size;
    const float* r_att  = (const float*)d_in[0];
    const float* p_att  = (const float*)d_in[1];
    const float* r_fun  = (const float*)d_in[2];
    const float* p_fun  = (const float*)d_in[3];
    const int*   idx    = (const int*)d_in[4];
    const float* W_att1 = (const float*)d_in[5];
    const float* b_att1 = (const float*)d_in[6];
    const float* W_att2 = (const float*)d_in[7];
    const float* b_att2 = (const float*)d_in[8];
    const float* W_fun1 = (const float*)d_in[9];
    const float* b_fun1 = (const float*)d_in[10];
    const float* W_fun2 = (const float*)d_in[11];
    const float* b_fun2 = (const float*)d_in[12];
    const float* W_out  = (const float*)d_in[17];
    float* d_out = (float*)d_out_;

    cudaMemcpyToSymbolAsync(c_w1,   d_in[13], 240  * sizeof(float), 0, cudaMemcpyDeviceToDevice);
    cudaMemcpyToSymbolAsync(c_b1,   d_in[14], 16   * sizeof(float), 0, cudaMemcpyDeviceToDevice);
    cudaMemcpyToSymbolAsync(c_w2,   d_in[15], 7680 * sizeof(float), 0, cudaMemcpyDeviceToDevice);
    cudaMemcpyToSymbolAsync(c_b2,   d_in[16], 32   * sizeof(float), 0, cudaMemcpyDeviceToDevice);
    cudaMemcpyToSymbolAsync(c_bout, d_in[18], 2    * sizeof(float), 0, cudaMemcpyDeviceToDevice);

    __half *a_att, *a_fun, *h_att, *h_fun;
    uint32_t *w_a1, *w_f1, *w_a2, *w_f2;
    float *pa, *pf;
    cudaGetSymbolAddress((void**)&a_att, g_a_att);
    cudaGetSymbolAddress((void**)&a_fun, g_a_fun);
    cudaGetSymbolAddress((void**)&h_att, g_h_att);
    cudaGetSymbolAddress((void**)&h_fun, g_h_fun);
    cudaGetSymbolAddress((void**)&w_a1, g_w_att1);
    cudaGetSymbolAddress((void**)&w_f1, g_w_fun1);
    cudaGetSymbolAddress((void**)&w_a2, g_w_att2);
    cudaGetSymbolAddress((void**)&w_f2, g_w_fun2);
    cudaGetSymbolAddress((void**)&pa, g_part_att);
    cudaGetSymbolAddress((void**)&pf, g_part_fun);

    dim3 blk(256);

    // pre-pass converts
    {
        long long nA1 = (long long)NM * (KA_ATT / 2);
        long long nA2 = (long long)NM * (KA_FUN / 2);
        cvtA<<<(unsigned)((nA1 + 255) / 256), blk>>>(r_att, p_att, NR, 3000, KA_ATT, a_att, NM);
        cvtA<<<(unsigned)((nA2 + 255) / 256), blk>>>(r_fun, p_fun, NR, 5603, KA_FUN, a_fun, NM);
        long long nW1 = (long long)NT_ATT1 * 16 * 2048;
        long long nW2 = (long long)NT_FUN1 * 16 * 4096;
        long long nW3 = (long long)64 * 16 * 256;
        long long nW4 = (long long)128 * 16 * 256;
        cvtW<<<(unsigned)((nW1 + 255) / 256), blk>>>(W_att1, 3000, 2048, NT_ATT1 * 16, w_a1);
        cvtW<<<(unsigned)((nW2 + 255) / 256), blk>>>(W_fun1, 5603, 4096, NT_FUN1 * 16, w_f1);
        cvtW<<<(unsigned)((nW3 + 255) / 256), blk>>>(W_att2, 2048, 256, 64 * 16, w_a2);
        cvtW<<<(unsigned)((nW4 + 255) / 256), blk>>>(W_fun2, 4096, 256, 128 * 16, w_f2);
    }

    // layer-1 merged (fun first: longest-job-first)
    GP Pfun1 = { a_fun, w_f1, b_fun1, h_fun, NM, 4096, KA_FUN, NT_FUN1, 32 };
    GP Patt1 = { a_att, w_a1, b_att1, h_att, NM, 2048, KA_ATT, NT_ATT1, 16 };
    // layer-2 merged split-K partials
    GP Pfun2 = { h_fun, w_f2, b_fun2, pf, NM, 256, 4096, 128 / SPLITK, 2 };
    GP Patt2 = { h_att, w_a2, b_att2, pa, NM, 256, 2048, 64 / SPLITK, 2 };

    const int nblk_fun1 = 28 * 32;            // 896
    const int nblk_att1 = 28 * 16;            // 448
    const int nblk_l2   = 28 * 2 * SPLITK;    // 224 each

    gemm_fp16<0><<<nblk_fun1 + nblk_att1, blk>>>(Pfun1, Patt1, nblk_fun1);
    gemm_fp16<2><<<2 * nblk_l2, blk>>>(Pfun2, Patt2, nblk_l2);
    l2_epilogue<<<(NM * 128 + 255) / 256, 256>>>(pa, pf, b_att2, b_fun2, d_out);
    conv_kernel<<<NSAMP, blk>>>(idx, W_out, d_out);
}

// round 15
// speedup vs baseline: 2.7328x; 1.8247x over previous
#include <cuda_runtime.h>
#include <cuda_fp16.h>
#include <math.h>
#include <stdint.h>

// ---------------- problem constants ----------------
#define NR 2000
#define NP 1512
#define NM 3512            // NR + NP
#define NSAMP 8192
#define SPLITK 4

#define E_P_OFS  ((size_t)NR * 512)                 // 1,024,000
#define OUT_OFS  (E_P_OFS + (size_t)NP * 512)       // 1,798,144
#define FLAT_OFS (OUT_OFS + (size_t)NSAMP * 2)      // 1,814,528

// padded K (fp16 elems, multiples of 32)
#define KA_ATT 3008        // 94 tiles
#define KA_FUN 5632        // 176 tiles
#define NT_ATT1 94
#define NT_FUN1 176

typedef unsigned long long ull;

// ---------------- scratch (no allocations allowed) ----------------
__device__ __align__(16) __half g_a_att[(size_t)NM * KA_ATT];
__device__ __align__(16) __half g_a_fun[(size_t)NM * KA_FUN];
__device__ __align__(16) __half g_h_att[(size_t)NM * 2048];
__device__ __align__(16) __half g_h_fun[(size_t)NM * 4096];
__device__ __align__(16) uint32_t g_w_att1[(size_t)NT_ATT1 * 16 * 2048];
__device__ __align__(16) uint32_t g_w_fun1[(size_t)NT_FUN1 * 16 * 4096];
__device__ __align__(16) uint32_t g_w_att2[(size_t)64 * 16 * 256];
__device__ __align__(16) uint32_t g_w_fun2[(size_t)128 * 16 * 256];
__device__ float g_part_att[(size_t)SPLITK * NM * 256];
__device__ float g_part_fun[(size_t)SPLITK * NM * 256];
// conv2 weights as 4 per-oh GEMM A matrices [4][32 oc][80 k-pair words]
__device__ __align__(16) uint32_t g_w2a[4 * 32 * 80];

// conv weights/biases in constant memory
__constant__ float c_w1[240];    // [16][3][5]
__constant__ float c_b1[16];
__constant__ float c_b2[32];
__constant__ float c_bout[2];

__device__ __forceinline__ float gelu_exact(float x) {
    return 0.5f * x * (1.0f + erff(x * 0.70710678118654752440f));
}

// ---------------- async copy + mma helpers ----------------
__device__ __forceinline__ uint32_t sptr(const void* p) {
    return (uint32_t)__cvta_generic_to_shared(p);
}
__device__ __forceinline__ void cpa16(uint32_t d, const void* s, int bytes) {
    asm volatile("cp.async.cg.shared.global [%0], [%1], 16, %2;\n"
                 :: "r"(d), "l"(s), "r"(bytes));
}
__device__ __forceinline__ void cp_commit() {
    asm volatile("cp.async.commit_group;\n");
}
__device__ __forceinline__ void cp_wait1() {
    asm volatile("cp.async.wait_group 1;\n" ::: "memory");
}
// fp16 mma m16n8k16, fp32 accumulate
__device__ __forceinline__ void mma_fp16(float* d, const uint32_t* a, const uint32_t* b) {
    asm volatile(
        "mma.sync.aligned.m16n8k16.row.col.f32.f16.f16.f32 "
        "{%0,%1,%2,%3}, {%4,%5,%6,%7}, {%8,%9}, {%0,%1,%2,%3};\n"
        : "+f"(d[0]), "+f"(d[1]), "+f"(d[2]), "+f"(d[3])
        : "r"(a[0]), "r"(a[1]), "r"(a[2]), "r"(a[3]), "r"(b[0]), "r"(b[1]));
}

// ---------------- pre-pass: fp32 -> fp16 converts ----------------
__global__ void __launch_bounds__(256)
cvtA(const float* __restrict__ s0, const float* __restrict__ s1, int n_r,
     int K, int Kpad, __half* __restrict__ dst, int M)
{
    long long u = (long long)blockIdx.x * 256 + threadIdx.x;
    int pairs = Kpad >> 1;
    if (u >= (long long)M * pairs) return;
    int row = (int)(u / pairs);
    int k = (int)(u % pairs) * 2;
    const float* s = (row < n_r) ? (s0 + (size_t)row * K)
                                 : (s1 + (size_t)(row - n_r) * K);
    float v0 = (k     < K) ? s[k]     : 0.f;
    float v1 = (k + 1 < K) ? s[k + 1] : 0.f;
    ((__half2*)dst)[u] = __floats2half2_rn(v0, v1);
}

__global__ void __launch_bounds__(256)
cvtW(const float* __restrict__ W, int K, int N, int rowsOut,
     uint32_t* __restrict__ dst)
{
    long long u = (long long)blockIdx.x * 256 + threadIdx.x;
    if (u >= (long long)rowsOut * N) return;
    int kp = (int)(u / N);
    int n  = (int)(u % N);
    int k = kp * 2;
    float v0 = (k     < K) ? W[(size_t)k * N + n]       : 0.f;
    float v1 = (k + 1 < K) ? W[(size_t)(k + 1) * N + n] : 0.f;
    __half2 h = __floats2half2_rn(v0, v1);
    dst[u] = *(uint32_t*)&h;
}

// conv2 weights -> per-oh A matrices.  k = ic*10 + ih*5 + kw ; kh = ih - oh + 2.
__global__ void __launch_bounds__(256)
cvtW2(const float* __restrict__ W2, uint32_t* __restrict__ dst)
{
    int u = blockIdx.x * 256 + threadIdx.x;
    if (u >= 4 * 32 * 80) return;
    int kp = u % 80;
    int oc = (u / 80) % 32;
    int oh = u / (80 * 32);
    float v[2];
#pragma unroll
    for (int q = 0; q < 2; q++) {
        int r = kp * 2 + q;
        int ic = r / 10, rem = r % 10;
        int ih = rem / 5, kw = rem % 5;
        int kh = ih - oh + 2;
        v[q] = (kh >= 0 && kh <= 2) ? W2[((oc * 16 + ic) * 3 + kh) * 5 + kw] : 0.f;
    }
    __half2 h = __floats2half2_rn(v[0], v[1]);
    dst[u] = *(uint32_t*)&h;
}

// ---------------- fp16 tensor-core GEMM (merged 2 problems / launch) ----------------
struct GP {
    const __half* A; const uint32_t* Wp; const float* bias; void* C;
    int M, N, strideA, chunkT, nN;
};

#define GLOAD(st, kt)                                                          \
  {                                                                            \
    {                                                                          \
      const __half* srcA = Aptr + (size_t)(kt) * 32 + aw0 * 2;                 \
      int ab = aval ? 16 : 0;                                                  \
      cpa16(sa + ((st) * 2048 + am * 16 + ((aw0)     ^ awz)) * 4, srcA,     ab); \
      cpa16(sa + ((st) * 2048 + am * 16 + ((aw0 + 4) ^ awz)) * 4, srcA + 8, ab); \
    }                                                                          \
    {                                                                          \
      const uint32_t* srcB = P.Wp + (size_t)((kt) * 16 + bkr) * P.N + bn + bn0;\
      cpa16(sb + ((st) * 2048 + bkr * 128 + ((bn0)     ^ bswz)) * 4, srcB,     16); \
      cpa16(sb + ((st) * 2048 + bkr * 128 + ((bn0 + 4) ^ bswz)) * 4, srcB + 4, 16); \
    }                                                                          \
    cp_commit();                                                               \
  }

template<int ACT>
__global__ void __launch_bounds__(256, 2)
gemm_fp16(GP Pa, GP Pb, int nblkA)
{
    __shared__ __align__(16) uint32_t As[2][128 * 16];
    __shared__ __align__(16) uint32_t Bs[2][16 * 128];

    const GP P = (blockIdx.x < (unsigned)nblkA) ? Pa : Pb;
    const int b = (blockIdx.x < (unsigned)nblkA) ? blockIdx.x : blockIdx.x - nblkA;
    const int mb = b % 28;
    const int r_ = b / 28;
    const int nb = r_ % P.nN;
    const int sk = r_ / P.nN;

    const int tid  = threadIdx.x;
    const int lane = tid & 31;
    const int warp = tid >> 5;
    const int bm = mb * 128;
    const int bn = nb * 128;
    const int wm = (warp & 3) * 32;
    const int wn = (warp >> 2) * 64;
    const int tbeg = sk * P.chunkT;

    const int am = tid >> 1;
    const int arow = bm + am;
    const bool aval = arow < P.M;
    const __half* Aptr = P.A + (size_t)(aval ? arow : 0) * P.strideA;
    const int aw0 = (tid & 1) * 8;
    const int awz = ((am >> 1) & 3) << 2;
    const uint32_t sa = sptr(&As[0][0]);

    const int bkr  = tid >> 4;
    const int bn0  = (tid & 15) * 8;
    const int bswz = (bkr & 3) << 3;
    const uint32_t sb = sptr(&Bs[0][0]);

    float acc[2][8][4];
#pragma unroll
    for (int i = 0; i < 2; i++)
#pragma unroll
        for (int j = 0; j < 8; j++)
#pragma unroll
            for (int q = 0; q < 4; q++) acc[i][j][q] = 0.f;

    const int fr = lane >> 2;
    const int fc = lane & 3;
    const int nT = P.chunkT;

    GLOAD(0, tbeg)

    for (int t = 0; t < nT; t++) {
        if (t + 1 < nT) {
            GLOAD((t + 1) & 1, tbeg + t + 1)
        } else {
            cp_commit();
        }
        cp_wait1();
        __syncthreads();

        const uint32_t* as = &As[t & 1][0];
        const uint32_t* bs = &Bs[t & 1][0];
#pragma unroll
        for (int kq = 0; kq < 2; kq++) {
            uint32_t af[2][4], bf[8][2];
#pragma unroll
            for (int i = 0; i < 2; i++) {
                const int row = wm + i * 16 + fr;
                const int swz = ((row >> 1) & 3) << 2;
                const uint32_t* p  = as + row * 16;
                const uint32_t* p8 = as + (row + 8) * 16;
                const int c0 = (kq * 8 + fc)     ^ swz;
                const int c4 = (kq * 8 + fc + 4) ^ swz;
                af[i][0] = p[c0];
                af[i][1] = p8[c0];
                af[i][2] = p[c4];
                af[i][3] = p8[c4];
            }
#pragma unroll
            for (int j = 0; j < 8; j++) {
                const int n = (wn + j * 8 + fr) ^ (fc << 3);
                bf[j][0] = bs[(kq * 8 + fc)     * 128 + n];
                bf[j][1] = bs[(kq * 8 + fc + 4) * 128 + n];
            }
#pragma unroll
            for (int i = 0; i < 2; i++)
#pragma unroll
                for (int j = 0; j < 8; j++)
                    mma_fp16(acc[i][j], af[i], bf[j]);
        }
        __syncthreads();
    }

#pragma unroll
    for (int i = 0; i < 2; i++) {
        const int m0 = bm + wm + i * 16 + fr;
#pragma unroll
        for (int j = 0; j < 8; j++) {
            const int n0 = bn + wn + j * 8 + fc * 2;
            if (ACT == 0) {
                __half* Ch = (__half*)P.C;
                float b0 = P.bias[n0], b1 = P.bias[n0 + 1];
                if (m0 < P.M) {
                    float v0 = gelu_exact(acc[i][j][0] + b0);
                    float v1 = gelu_exact(acc[i][j][1] + b1);
                    *(__half2*)(Ch + (size_t)m0 * P.N + n0) = __floats2half2_rn(v0, v1);
                }
                if (m0 + 8 < P.M) {
                    float v2 = gelu_exact(acc[i][j][2] + b0);
                    float v3 = gelu_exact(acc[i][j][3] + b1);
                    *(__half2*)(Ch + (size_t)(m0 + 8) * P.N + n0) = __floats2half2_rn(v2, v3);
                }
            } else {
                float* Cf = (float*)P.C + (size_t)sk * P.M * P.N;
                if (m0 < P.M) {
                    Cf[(size_t)m0 * P.N + n0]     = acc[i][j][0];
                    Cf[(size_t)m0 * P.N + n0 + 1] = acc[i][j][1];
                }
                if (m0 + 8 < P.M) {
                    Cf[(size_t)(m0 + 8) * P.N + n0]     = acc[i][j][2];
                    Cf[(size_t)(m0 + 8) * P.N + n0 + 1] = acc[i][j][3];
                }
            }
        }
    }
}

// ---------------- layer-2 split-K reduce + bias + sigmoid + scatter ----------------
__global__ void __launch_bounds__(256)
l2_epilogue(const float* __restrict__ pa, const float* __restrict__ pf,
            const float* __restrict__ ba, const float* __restrict__ bf,
            float* __restrict__ d_out)
{
    int t = blockIdx.x * blockDim.x + threadIdx.x;
    if (t >= NM * 128) return;
    int m  = t >> 7;
    int c4 = (t & 127) * 4;
    const float* src;
    const float* bb;
    int c;
    if (c4 < 256) { src = pa + (size_t)m * 256 + c4;         bb = ba; c = c4; }
    else          { src = pf + (size_t)m * 256 + (c4 - 256); bb = bf; c = c4 - 256; }
    float v[4];
#pragma unroll
    for (int q = 0; q < 4; q++) {
        float s = bb[c + q];
#pragma unroll
        for (int sk = 0; sk < SPLITK; sk++)
            s += src[(size_t)sk * NM * 256 + q];
        v[q] = 1.f / (1.f + expf(-s));
    }
    size_t dst = (m < NR) ? ((size_t)m * 512 + c4)
                          : (E_P_OFS + (size_t)(m - NR) * 512 + c4);
    *(float4*)(d_out + dst) = make_float4(v[0], v[1], v[2], v[3]);
}

// ---------------- conv: gather + conv1(fp32)+pool -> im2col fp16 -> mma conv2
//                  + maxpool + tanh + flat + out-dot, one block per sample ----
// Bt smem: [ow 0..255][k' 0..79 pair-words], stride 84 words (bank-conflict-free frags)
// A (per-oh weights) from global g_w2a[4][32][80], L1-resident.
#define BT_STRIDE 84
#define CONV_SMEM (256 * BT_STRIDE * 4 + 2 * 516 * 4 + 64)

__global__ void __launch_bounds__(256)
conv_kernel(const int* __restrict__ idx, const float* __restrict__ W_out,
            const uint32_t* __restrict__ w2a, float* __restrict__ d_out)
{
    extern __shared__ char dsm[];
    uint32_t* Btw = (uint32_t*)dsm;                          // 21504 words
    __half*   Bth = (__half*)dsm;                            // same, half view
    float* xp  = (float*)(dsm + 256 * BT_STRIDE * 4);        // [2][516]
    float* red = (float*)(dsm + 256 * BT_STRIDE * 4 + 2 * 516 * 4);

    const int s = blockIdx.x;
    const int tid = threadIdx.x;
    const int w = tid >> 5, l = tid & 31;
    const int fr = l >> 2, fc = l & 3;

    const int id = idx[s];
    const int r_no = id / 1512;
    const int p_no = id % 1512;
    const float* er = d_out + (size_t)r_no * 512;
    const float* ep = d_out + E_P_OFS + (size_t)p_no * 512;

    // load input rows with halo
    for (int t = tid; t < 2 * 516; t += 256) {
        int row = (t >= 516);
        int c = row ? (t - 516) : t;
        int iw = c - 2;
        float v = 0.f;
        if (iw >= 0 && iw < 512) v = row ? ep[iw] : er[iw];
        xp[row * 516 + c] = v;
    }
    // zero Bt edge cells never written by the scatter: (kw,ow) in
    // {(0,0),(0,1),(1,0),(3,255),(4,254),(4,255)} x 32 (ic,ih)
    if (tid < 192) {
        const int kwt[6] = {0, 0, 1, 3, 4, 4};
        const int owt[6] = {0, 1, 0, 255, 254, 255};
        int cse = tid / 32, pair = tid & 31;
        int ic = pair >> 1, ih = pair & 1;
        Bth[owt[cse] * (BT_STRIDE * 2) + ic * 10 + ih * 5 + kwt[cse]] = __float2half(0.f);
    }
    __syncthreads();

    // ---- conv1 (3x5, pad 2) + leaky + avgpool(2x2) -> fp16 im2col scatter ----
#pragma unroll
    for (int ph = 0; ph < 2; ph++) {
#pragma unroll
        for (int j = 0; j < 8; j++) {
            int pw = l + 32 * j;
            float t0[6], t1[6];
#pragma unroll
            for (int q = 0; q < 6; q++) { t0[q] = xp[2 * pw + q]; t1[q] = xp[516 + 2 * pw + q]; }
#pragma unroll
            for (int oi = 0; oi < 2; oi++) {
                int oc = w + 8 * oi;
                float b = c_b1[oc];
                float v00 = b, v01 = b, v10 = b, v11 = b;
#pragma unroll
                for (int kw = 0; kw < 5; kw++) {
                    float w0 = c_w1[oc * 15 + 0 + kw];
                    float w1 = c_w1[oc * 15 + 5 + kw];
                    float w2 = c_w1[oc * 15 + 10 + kw];
                    if (ph == 0) {
                        v00 += t0[kw] * w2;                 v01 += t0[kw + 1] * w2;
                        v10 += t0[kw] * w1 + t1[kw] * w2;   v11 += t0[kw + 1] * w1 + t1[kw + 1] * w2;
                    } else {
                        v00 += t0[kw] * w0 + t1[kw] * w1;   v01 += t0[kw + 1] * w0 + t1[kw + 1] * w1;
                        v10 += t1[kw] * w0;                 v11 += t1[kw + 1] * w0;
                    }
                }
                float lk00 = v00 >= 0.f ? v00 : 0.01f * v00;
                float lk01 = v01 >= 0.f ? v01 : 0.01f * v01;
                float lk10 = v10 >= 0.f ? v10 : 0.01f * v10;
                float lk11 = v11 >= 0.f ? v11 : 0.01f * v11;
                __half hv = __float2half(0.25f * (lk00 + lk01 + lk10 + lk11));
                // scatter to im2col rows r = oc*10 + ph*5 + kw at ow = pw + 2 - kw
                int rbase = oc * 10 + ph * 5;
#pragma unroll
                for (int kw = 0; kw < 5; kw++) {
                    int ow = pw + 2 - kw;
                    if (ow >= 0 && ow <= 255)
                        Bth[ow * (BT_STRIDE * 2) + rbase + kw] = hv;
                }
            }
        }
    }
    __syncthreads();

    // ---- conv2 via mma: warp -> (ph = w&1, oc-half, ow-half) ----
    const int ph  = w & 1;
    const int ocb = ((w >> 1) & 1) * 16;
    const int owh = (w >> 2) * 128;
    const uint32_t* A0 = w2a + (size_t)(2 * ph)     * 32 * 80;
    const uint32_t* A1 = w2a + (size_t)(2 * ph + 1) * 32 * 80;

    float p0 = 0.f, p1 = 0.f;
#pragma unroll 1
    for (int c = 0; c < 4; c++) {
        float acc[2][4][4];
#pragma unroll
        for (int o = 0; o < 2; o++)
#pragma unroll
            for (int j = 0; j < 4; j++)
#pragma unroll
                for (int q = 0; q < 4; q++) acc[o][j][q] = 0.f;

#pragma unroll
        for (int ks = 0; ks < 10; ks++) {
            uint32_t a[2][4];
            const int k0 = ks * 8 + fc;
            a[0][0] = __ldg(A0 + (ocb + fr) * 80 + k0);
            a[0][1] = __ldg(A0 + (ocb + fr + 8) * 80 + k0);
            a[0][2] = __ldg(A0 + (ocb + fr) * 80 + k0 + 4);
            a[0][3] = __ldg(A0 + (ocb + fr + 8) * 80 + k0 + 4);
            a[1][0] = __ldg(A1 + (ocb + fr) * 80 + k0);
            a[1][1] = __ldg(A1 + (ocb + fr + 8) * 80 + k0);
            a[1][2] = __ldg(A1 + (ocb + fr) * 80 + k0 + 4);
            a[1][3] = __ldg(A1 + (ocb + fr + 8) * 80 + k0 + 4);
#pragma unroll
            for (int j = 0; j < 4; j++) {
                const int n = owh + c * 32 + j * 8 + fr;
                uint32_t bb[2];
                bb[0] = Btw[n * BT_STRIDE + k0];
                bb[1] = Btw[n * BT_STRIDE + k0 + 4];
                mma_fp16(acc[0][j], a[0], bb);
                mma_fp16(acc[1][j], a[1], bb);
            }
        }
        // maxpool (oh pair in acc[0]/acc[1]; ow pair = c-frag cols) + bias + leaky + tanh
#pragma unroll
        for (int j = 0; j < 4; j++) {
#pragma unroll
            for (int h = 0; h < 2; h++) {
                int oc = ocb + fr + 8 * h;
                float m = fmaxf(fmaxf(acc[0][j][2 * h], acc[0][j][2 * h + 1]),
                                fmaxf(acc[1][j][2 * h], acc[1][j][2 * h + 1]));
                m += c_b2[oc];
                float lv = m >= 0.f ? m : 0.01f * m;
                float val = tanhf(lv);
                int pw = (owh >> 1) + c * 16 + j * 4 + fc;
                int fidx = oc * 256 + ph * 128 + pw;
                d_out[FLAT_OFS + (size_t)s * 8192 + fidx] = val;
                p0 += val * __ldg(W_out + 2 * fidx);
                p1 += val * __ldg(W_out + 2 * fidx + 1);
            }
        }
    }

    // block-reduce output dot
#pragma unroll
    for (int off = 16; off > 0; off >>= 1) {
        p0 += __shfl_xor_sync(0xffffffffu, p0, off);
        p1 += __shfl_xor_sync(0xffffffffu, p1, off);
    }
    if (l == 0) { red[w] = p0; red[8 + w] = p1; }
    __syncthreads();
    if (tid == 0) {
        float s0 = c_bout[0], s1 = c_bout[1];
#pragma unroll
        for (int q = 0; q < 8; q++) { s0 += red[q]; s1 += red[8 + q]; }
        d_out[OUT_OFS + 2 * (size_t)s]     = s0;
        d_out[OUT_OFS + 2 * (size_t)s + 1] = s1;
    }
}

// ---------------- launch ----------------
extern "C" void kernel_launch(void* const* d_in, const int* in_sizes, int n_in,
                              void* d_out_, int out_size)
{
    (void)in_sizes; (void)n_in; (void)out_size;
    const float* r_att  = (const float*)d_in[0];
    const float* p_att  = (const float*)d_in[1];
    const float* r_fun  = (const float*)d_in[2];
    const float* p_fun  = (const float*)d_in[3];
    const int*   idx    = (const int*)d_in[4];
    const float* W_att1 = (const float*)d_in[5];
    const float* b_att1 = (const float*)d_in[6];
    const float* W_att2 = (const float*)d_in[7];
    const float* b_att2 = (const float*)d_in[8];
    const float* W_fun1 = (const float*)d_in[9];
    const float* b_fun1 = (const float*)d_in[10];
    const float* W_fun2 = (const float*)d_in[11];
    const float* b_fun2 = (const float*)d_in[12];
    const float* conv2w = (const float*)d_in[15];
    const float* W_out  = (const float*)d_in[17];
    float* d_out = (float*)d_out_;

    cudaMemcpyToSymbolAsync(c_w1,   d_in[13], 240 * sizeof(float), 0, cudaMemcpyDeviceToDevice);
    cudaMemcpyToSymbolAsync(c_b1,   d_in[14], 16  * sizeof(float), 0, cudaMemcpyDeviceToDevice);
    cudaMemcpyToSymbolAsync(c_b2,   d_in[16], 32  * sizeof(float), 0, cudaMemcpyDeviceToDevice);
    cudaMemcpyToSymbolAsync(c_bout, d_in[18], 2   * sizeof(float), 0, cudaMemcpyDeviceToDevice);

    __half *a_att, *a_fun, *h_att, *h_fun;
    uint32_t *w_a1, *w_f1, *w_a2, *w_f2, *w2a;
    float *pa, *pf;
    cudaGetSymbolAddress((void**)&a_att, g_a_att);
    cudaGetSymbolAddress((void**)&a_fun, g_a_fun);
    cudaGetSymbolAddress((void**)&h_att, g_h_att);
    cudaGetSymbolAddress((void**)&h_fun, g_h_fun);
    cudaGetSymbolAddress((void**)&w_a1, g_w_att1);
    cudaGetSymbolAddress((void**)&w_f1, g_w_fun1);
    cudaGetSymbolAddress((void**)&w_a2, g_w_att2);
    cudaGetSymbolAddress((void**)&w_f2, g_w_fun2);
    cudaGetSymbolAddress((void**)&w2a, g_w2a);
    cudaGetSymbolAddress((void**)&pa, g_part_att);
    cudaGetSymbolAddress((void**)&pf, g_part_fun);

    cudaFuncSetAttribute(conv_kernel, cudaFuncAttributeMaxDynamicSharedMemorySize, CONV_SMEM);

    dim3 blk(256);

    // pre-pass converts
    {
        long long nA1 = (long long)NM * (KA_ATT / 2);
        long long nA2 = (long long)NM * (KA_FUN / 2);
        cvtA<<<(unsigned)((nA1 + 255) / 256), blk>>>(r_att, p_att, NR, 3000, KA_ATT, a_att, NM);
        cvtA<<<(unsigned)((nA2 + 255) / 256), blk>>>(r_fun, p_fun, NR, 5603, KA_FUN, a_fun, NM);
        long long nW1 = (long long)NT_ATT1 * 16 * 2048;
        long long nW2 = (long long)NT_FUN1 * 16 * 4096;
        long long nW3 = (long long)64 * 16 * 256;
        long long nW4 = (long long)128 * 16 * 256;
        cvtW<<<(unsigned)((nW1 + 255) / 256), blk>>>(W_att1, 3000, 2048, NT_ATT1 * 16, w_a1);
        cvtW<<<(unsigned)((nW2 + 255) / 256), blk>>>(W_fun1, 5603, 4096, NT_FUN1 * 16, w_f1);
        cvtW<<<(unsigned)((nW3 + 255) / 256), blk>>>(W_att2, 2048, 256, 64 * 16, w_a2);
        cvtW<<<(unsigned)((nW4 + 255) / 256), blk>>>(W_fun2, 4096, 256, 128 * 16, w_f2);
        cvtW2<<<(4 * 32 * 80 + 255) / 256, blk>>>(conv2w, w2a);
    }

    // layer-1 merged (fun first: longest-job-first)
    GP Pfun1 = { a_fun, w_f1, b_fun1, h_fun, NM, 4096, KA_FUN, NT_FUN1, 32 };
    GP Patt1 = { a_att, w_a1, b_att1, h_att, NM, 2048, KA_ATT, NT_ATT1, 16 };
    // layer-2 merged split-K partials
    GP Pfun2 = { h_fun, w_f2, b_fun2, pf, NM, 256, 4096, 128 / SPLITK, 2 };
    GP Patt2 = { h_att, w_a2, b_att2, pa, NM, 256, 2048, 64 / SPLITK, 2 };

    const int nblk_fun1 = 28 * 32;            // 896
    const int nblk_att1 = 28 * 16;            // 448
    const int nblk_l2   = 28 * 2 * SPLITK;    // 224 each

    gemm_fp16<0><<<nblk_fun1 + nblk_att1, blk>>>(Pfun1, Patt1, nblk_fun1);
    gemm_fp16<2><<<2 * nblk_l2, blk>>>(Pfun2, Patt2, nblk_l2);
    l2_epilogue<<<(NM * 128 + 255) / 256, 256>>>(pa, pf, b_att2, b_fun2, d_out);
    conv_kernel<<<NSAMP, blk, CONV_SMEM>>>(idx, W_out, w2a, d_out);
}